// round 4
// baseline (speedup 1.0000x reference)
#include <cuda_runtime.h>
#include <math.h>

// Problem shapes (fixed by the dataset)
static constexpr int S = 2048;
static constexpr int B = 32;
static constexpr int E = 1024;
static constexpr int A = 1024;
static constexpr int D = 1024;
static constexpr int R = S * B;          // 65536 rows of the big GEMM
static constexpr int NT = A / 128;       // 8 column tiles -> 8 energy partials/row
static constexpr int SCH = 16;           // s-chunks for context kernel

// Scratch (no allocation allowed -> __device__ globals)
__device__ float g_z0[B * A];            // dec_proj + bias          (128 KB)
__device__ float g_epart[NT * R];        // energy partials           (2 MB)
__device__ float g_p[R];                 // p_choose                  (256 KB)
__device__ float g_ctx[SCH * B * E];     // context partials          (2 MB)

// ---------------------------------------------------------------------------
// Kernel 1: z0[b,a] = decoder_state[b,:] @ W_dec[:,a] + bias[a]
// ---------------------------------------------------------------------------
__global__ void k_decproj(const float* __restrict__ dec,
                          const float* __restrict__ Wdec,
                          const float* __restrict__ bias) {
    __shared__ float sd[D];
    const int b = blockIdx.x;
    const int tid = threadIdx.x;
    for (int i = tid; i < D; i += 256) sd[i] = dec[b * D + i];
    __syncthreads();

    float a0 = 0.f, a1 = 0.f, a2 = 0.f, a3 = 0.f;
#pragma unroll 4
    for (int e = 0; e < D; e++) {
        const float dv = sd[e];
        const float* w = Wdec + (size_t)e * A + tid;
        a0 += dv * w[0];
        a1 += dv * w[256];
        a2 += dv * w[512];
        a3 += dv * w[768];
    }
    g_z0[b * A + tid + 0]   = a0 + bias[tid + 0];
    g_z0[b * A + tid + 256] = a1 + bias[tid + 256];
    g_z0[b * A + tid + 512] = a2 + bias[tid + 512];
    g_z0[b * A + tid + 768] = a3 + bias[tid + 768];
}

// ---------------------------------------------------------------------------
// Kernel 2: fused GEMM + tanh + v-dot epilogue.
//   enc_flat [R, E] (row r = s*B + b) times W_enc [E, A].
//   Block tile: 128 rows x 128 cols x 16 K. 256 threads, 8x8 per thread.
//   Epilogue: t = tanh(acc + z0[r%32, a]); partial[r] += v[a]*t, reduced
//   across the 16 threads covering a row, written (NO atomics -> deterministic)
//   to g_epart[blockIdx.x][r].
// ---------------------------------------------------------------------------
__global__ __launch_bounds__(256, 2)
void k_gemm_energy(const float* __restrict__ enc,
                   const float* __restrict__ Wenc,
                   const float* __restrict__ v) {
    constexpr int BM = 128, BN = 128, BK = 16;
    __shared__ float As[BK][BM];       // transposed A tile
    __shared__ float Bs[BK][BN];
    __shared__ float red[BM][17];      // padded row-reduction scratch

    const int tid = threadIdx.x;
    const int tx = tid & 15;           // n direction (8 cols each)
    const int ty = tid >> 4;           // m direction (8 rows each)
    const int r0 = blockIdx.y * BM;
    const int a0 = blockIdx.x * BN;

    // loader indices
    const int arow = tid >> 2;                 // 0..63
    const int acol = (tid & 3) * 4;            // 0,4,8,12
    const int brow = tid >> 5;                 // 0..7
    const int bcol = (tid & 31) * 4;           // 0..124

    float acc[8][8];
#pragma unroll
    for (int i = 0; i < 8; i++)
#pragma unroll
        for (int j = 0; j < 8; j++) acc[i][j] = 0.f;

    const float* Aptr = enc + (size_t)(r0 + arow) * E + acol;
    const float* Bptr = Wenc + (size_t)brow * A + a0 + bcol;

    for (int k0 = 0; k0 < E; k0 += BK) {
        const float4 av0 = *(const float4*)(Aptr + k0);
        const float4 av1 = *(const float4*)(Aptr + (size_t)64 * E + k0);
        const float4 bv0 = *(const float4*)(Bptr + (size_t)k0 * A);
        const float4 bv1 = *(const float4*)(Bptr + (size_t)(k0 + 8) * A);

        As[acol + 0][arow] = av0.x;  As[acol + 1][arow] = av0.y;
        As[acol + 2][arow] = av0.z;  As[acol + 3][arow] = av0.w;
        As[acol + 0][arow + 64] = av1.x;  As[acol + 1][arow + 64] = av1.y;
        As[acol + 2][arow + 64] = av1.z;  As[acol + 3][arow + 64] = av1.w;
        *(float4*)&Bs[brow][bcol]     = bv0;
        *(float4*)&Bs[brow + 8][bcol] = bv1;
        __syncthreads();

#pragma unroll
        for (int k = 0; k < BK; k++) {
            const float4 fa0 = *(const float4*)&As[k][ty * 8];
            const float4 fa1 = *(const float4*)&As[k][ty * 8 + 4];
            const float4 fb0 = *(const float4*)&Bs[k][tx * 8];
            const float4 fb1 = *(const float4*)&Bs[k][tx * 8 + 4];
            const float af[8] = {fa0.x, fa0.y, fa0.z, fa0.w, fa1.x, fa1.y, fa1.z, fa1.w};
            const float bf[8] = {fb0.x, fb0.y, fb0.z, fb0.w, fb1.x, fb1.y, fb1.z, fb1.w};
#pragma unroll
            for (int i = 0; i < 8; i++)
#pragma unroll
                for (int j = 0; j < 8; j++) acc[i][j] += af[i] * bf[j];
        }
        __syncthreads();
    }

    // Epilogue: tanh + dot with v, row-reduce.
    float vj[8];
#pragma unroll
    for (int j = 0; j < 8; j++) vj[j] = __ldg(&v[a0 + tx * 8 + j]);

#pragma unroll
    for (int i = 0; i < 8; i++) {
        const int m = ty * 8 + i;
        const int bb = (r0 + m) & 31;               // b = row % 32
        const float* zrow = g_z0 + (size_t)bb * A + a0 + tx * 8;
        float s = 0.f;
#pragma unroll
        for (int j = 0; j < 8; j++) {
            const float t = tanhf(acc[i][j] + zrow[j]);
            s += vj[j] * t;
        }
        red[m][tx] = s;
    }
    __syncthreads();

    if (tid < BM) {
        float s = 0.f;
#pragma unroll
        for (int c = 0; c < 16; c++) s += red[tid][c];
        g_epart[(size_t)blockIdx.x * R + r0 + tid] = s;
    }
}

// ---------------------------------------------------------------------------
// Kernel 3: p[r] = sigmoid(sum of 8 partials + noise[r])
// ---------------------------------------------------------------------------
__global__ void k_p(const float* __restrict__ noise) {
    const int i = blockIdx.x * 256 + threadIdx.x;
    if (i >= R) return;
    float s = 0.f;
#pragma unroll
    for (int c = 0; c < NT; c++) s += g_epart[(size_t)c * R + i];
    s += noise[i];
    g_p[i] = 1.f / (1.f + expf(-s));
}

// ---------------------------------------------------------------------------
// Kernel 4: sequential scan per batch column (32 independent chains).
//   alpha[s] = p[s] * exclusive_cumprod(1-p)[s]; last frame gets residual.
//   Chunked loads to keep the dependency chain (cp *= 1-p, 4 cyc) the only
//   serial part.
// ---------------------------------------------------------------------------
__global__ void k_scan(float* __restrict__ alpha) {
    const int lane = threadIdx.x;
    if (lane >= B) return;
    float cp = 1.f, run = 0.f;
    constexpr int CH = 8;
    for (int s0 = 0; s0 < S; s0 += CH) {
        float buf[CH];
#pragma unroll
        for (int i = 0; i < CH; i++) buf[i] = g_p[(s0 + i) * B + lane];
#pragma unroll
        for (int i = 0; i < CH; i++) {
            const int s = s0 + i;
            const float pp = buf[i];
            const float al = pp * cp;
            cp *= (1.f - pp);
            if (s < S - 1) {
                alpha[s * B + lane] = al;
                run += al;
            }
        }
    }
    run = fminf(fmaxf(run, 0.f), 1.f);
    alpha[(S - 1) * B + lane] = 1.f - run;
}

// ---------------------------------------------------------------------------
// Kernel 5: context partials. Grid (SCH s-chunks, B). Each block streams its
//   128 s-slices of enc[s,b,:] (4 KB coalesced each) -> deterministic partial.
// ---------------------------------------------------------------------------
__global__ void k_ctx(const float* __restrict__ enc,
                      const float* __restrict__ alpha) {
    const int sc = blockIdx.x;
    const int b = blockIdx.y;
    const int tid = threadIdx.x;
    const int s0 = sc * (S / SCH);
    float4 acc = make_float4(0.f, 0.f, 0.f, 0.f);
#pragma unroll 4
    for (int s = s0; s < s0 + S / SCH; s++) {
        const float al = __ldg(&alpha[s * B + b]);
        const float4 h = *(const float4*)(enc + ((size_t)(s * B + b)) * E + tid * 4);
        acc.x += al * h.x;  acc.y += al * h.y;
        acc.z += al * h.z;  acc.w += al * h.w;
    }
    *(float4*)&g_ctx[((size_t)(sc * B + b)) * E + tid * 4] = acc;
}

// ---------------------------------------------------------------------------
// Kernel 6: reduce the 16 context partials -> weighted_context.
// ---------------------------------------------------------------------------
__global__ void k_ctxred(float* __restrict__ out) {
    const int i = blockIdx.x * 256 + threadIdx.x;
    if (i >= B * E) return;
    float s = 0.f;
#pragma unroll
    for (int c = 0; c < SCH; c++) s += g_ctx[(size_t)c * B * E + i];
    out[i] = s;
}

// ---------------------------------------------------------------------------
extern "C" void kernel_launch(void* const* d_in, const int* in_sizes, int n_in,
                              void* d_out, int out_size) {
    const float* dec   = (const float*)d_in[0];   // [B, D]
    const float* enc   = (const float*)d_in[1];   // [S, B, E]
    const float* noise = (const float*)d_in[2];   // [S, B]
    const float* Wdec  = (const float*)d_in[3];   // [D, A]
    const float* Wenc  = (const float*)d_in[4];   // [E, A]
    const float* bias  = (const float*)d_in[5];   // [A]
    const float* v     = (const float*)d_in[6];   // [A]

    float* out       = (float*)d_out;             // [B*E] weighted_context
    float* alpha_out = out + B * E;               // [S*B] alpha

    k_decproj<<<B, 256>>>(dec, Wdec, bias);

    dim3 gg(NT, R / 128);
    k_gemm_energy<<<gg, 256>>>(enc, Wenc, v);

    k_p<<<R / 256, 256>>>(noise);

    k_scan<<<1, 32>>>(alpha_out);

    dim3 gc(SCH, B);
    k_ctx<<<gc, 256>>>(enc, alpha_out);

    k_ctxred<<<(B * E) / 256, 256>>>(out);
}

// round 5
// speedup vs baseline: 1.0001x; 1.0001x over previous
#include <cuda_runtime.h>
#include <math.h>

// Problem shapes (fixed by the dataset)
static constexpr int S = 2048;
static constexpr int B = 32;
static constexpr int E = 1024;
static constexpr int A = 1024;
static constexpr int D = 1024;
static constexpr int R = S * B;          // 65536 rows of the big GEMM
static constexpr int NT = A / 128;       // 8 column tiles -> 8 energy partials/row
static constexpr int SCH = 16;           // s-chunks for context kernel

// Scratch (no allocation allowed -> __device__ globals)
__device__ float g_z0[B * A];            // dec_proj + bias          (128 KB)
__device__ float g_epart[NT * R];        // energy partials           (2 MB)
__device__ float g_p[R];                 // p_choose                  (256 KB)
__device__ float g_ctx[SCH * B * E];     // context partials          (2 MB)

// ---------------------------------------------------------------------------
// Kernel 1: z0[b,a] = decoder_state[b,:] @ W_dec[:,a] + bias[a]
// ---------------------------------------------------------------------------
__global__ void k_decproj(const float* __restrict__ dec,
                          const float* __restrict__ Wdec,
                          const float* __restrict__ bias) {
    __shared__ float sd[D];
    const int b = blockIdx.x;
    const int tid = threadIdx.x;
    for (int i = tid; i < D; i += 256) sd[i] = dec[b * D + i];
    __syncthreads();

    float a0 = 0.f, a1 = 0.f, a2 = 0.f, a3 = 0.f;
#pragma unroll 4
    for (int e = 0; e < D; e++) {
        const float dv = sd[e];
        const float* w = Wdec + (size_t)e * A + tid;
        a0 += dv * w[0];
        a1 += dv * w[256];
        a2 += dv * w[512];
        a3 += dv * w[768];
    }
    g_z0[b * A + tid + 0]   = a0 + bias[tid + 0];
    g_z0[b * A + tid + 256] = a1 + bias[tid + 256];
    g_z0[b * A + tid + 512] = a2 + bias[tid + 512];
    g_z0[b * A + tid + 768] = a3 + bias[tid + 768];
}

// ---------------------------------------------------------------------------
// Kernel 2: fused GEMM + tanh + v-dot epilogue.
//   enc_flat [R, E] (row r = s*B + b) times W_enc [E, A].
//   Block tile: 128 rows x 128 cols x 16 K. 256 threads, 8x8 per thread.
//   Epilogue: t = tanh(acc + z0[r%32, a]); partial[r] += v[a]*t, reduced
//   across the 16 threads covering a row, written (NO atomics -> deterministic)
//   to g_epart[blockIdx.x][r].
// ---------------------------------------------------------------------------
__global__ __launch_bounds__(256, 2)
void k_gemm_energy(const float* __restrict__ enc,
                   const float* __restrict__ Wenc,
                   const float* __restrict__ v) {
    constexpr int BM = 128, BN = 128, BK = 16;
    __shared__ float As[BK][BM];       // transposed A tile
    __shared__ float Bs[BK][BN];
    __shared__ float red[BM][17];      // padded row-reduction scratch

    const int tid = threadIdx.x;
    const int tx = tid & 15;           // n direction (8 cols each)
    const int ty = tid >> 4;           // m direction (8 rows each)
    const int r0 = blockIdx.y * BM;
    const int a0 = blockIdx.x * BN;

    // loader indices
    const int arow = tid >> 2;                 // 0..63
    const int acol = (tid & 3) * 4;            // 0,4,8,12
    const int brow = tid >> 5;                 // 0..7
    const int bcol = (tid & 31) * 4;           // 0..124

    float acc[8][8];
#pragma unroll
    for (int i = 0; i < 8; i++)
#pragma unroll
        for (int j = 0; j < 8; j++) acc[i][j] = 0.f;

    const float* Aptr = enc + (size_t)(r0 + arow) * E + acol;
    const float* Bptr = Wenc + (size_t)brow * A + a0 + bcol;

    for (int k0 = 0; k0 < E; k0 += BK) {
        const float4 av0 = *(const float4*)(Aptr + k0);
        const float4 av1 = *(const float4*)(Aptr + (size_t)64 * E + k0);
        const float4 bv0 = *(const float4*)(Bptr + (size_t)k0 * A);
        const float4 bv1 = *(const float4*)(Bptr + (size_t)(k0 + 8) * A);

        As[acol + 0][arow] = av0.x;  As[acol + 1][arow] = av0.y;
        As[acol + 2][arow] = av0.z;  As[acol + 3][arow] = av0.w;
        As[acol + 0][arow + 64] = av1.x;  As[acol + 1][arow + 64] = av1.y;
        As[acol + 2][arow + 64] = av1.z;  As[acol + 3][arow + 64] = av1.w;
        *(float4*)&Bs[brow][bcol]     = bv0;
        *(float4*)&Bs[brow + 8][bcol] = bv1;
        __syncthreads();

#pragma unroll
        for (int k = 0; k < BK; k++) {
            const float4 fa0 = *(const float4*)&As[k][ty * 8];
            const float4 fa1 = *(const float4*)&As[k][ty * 8 + 4];
            const float4 fb0 = *(const float4*)&Bs[k][tx * 8];
            const float4 fb1 = *(const float4*)&Bs[k][tx * 8 + 4];
            const float af[8] = {fa0.x, fa0.y, fa0.z, fa0.w, fa1.x, fa1.y, fa1.z, fa1.w};
            const float bf[8] = {fb0.x, fb0.y, fb0.z, fb0.w, fb1.x, fb1.y, fb1.z, fb1.w};
#pragma unroll
            for (int i = 0; i < 8; i++)
#pragma unroll
                for (int j = 0; j < 8; j++) acc[i][j] += af[i] * bf[j];
        }
        __syncthreads();
    }

    // Epilogue: tanh + dot with v, row-reduce.
    float vj[8];
#pragma unroll
    for (int j = 0; j < 8; j++) vj[j] = __ldg(&v[a0 + tx * 8 + j]);

#pragma unroll
    for (int i = 0; i < 8; i++) {
        const int m = ty * 8 + i;
        const int bb = (r0 + m) & 31;               // b = row % 32
        const float* zrow = g_z0 + (size_t)bb * A + a0 + tx * 8;
        float s = 0.f;
#pragma unroll
        for (int j = 0; j < 8; j++) {
            const float t = tanhf(acc[i][j] + zrow[j]);
            s += vj[j] * t;
        }
        red[m][tx] = s;
    }
    __syncthreads();

    if (tid < BM) {
        float s = 0.f;
#pragma unroll
        for (int c = 0; c < 16; c++) s += red[tid][c];
        g_epart[(size_t)blockIdx.x * R + r0 + tid] = s;
    }
}

// ---------------------------------------------------------------------------
// Kernel 3: p[r] = sigmoid(sum of 8 partials + noise[r])
// ---------------------------------------------------------------------------
__global__ void k_p(const float* __restrict__ noise) {
    const int i = blockIdx.x * 256 + threadIdx.x;
    if (i >= R) return;
    float s = 0.f;
#pragma unroll
    for (int c = 0; c < NT; c++) s += g_epart[(size_t)c * R + i];
    s += noise[i];
    g_p[i] = 1.f / (1.f + expf(-s));
}

// ---------------------------------------------------------------------------
// Kernel 4: sequential scan per batch column (32 independent chains).
//   alpha[s] = p[s] * exclusive_cumprod(1-p)[s]; last frame gets residual.
//   Chunked loads to keep the dependency chain (cp *= 1-p, 4 cyc) the only
//   serial part.
// ---------------------------------------------------------------------------
__global__ void k_scan(float* __restrict__ alpha) {
    const int lane = threadIdx.x;
    if (lane >= B) return;
    float cp = 1.f, run = 0.f;
    constexpr int CH = 8;
    for (int s0 = 0; s0 < S; s0 += CH) {
        float buf[CH];
#pragma unroll
        for (int i = 0; i < CH; i++) buf[i] = g_p[(s0 + i) * B + lane];
#pragma unroll
        for (int i = 0; i < CH; i++) {
            const int s = s0 + i;
            const float pp = buf[i];
            const float al = pp * cp;
            cp *= (1.f - pp);
            if (s < S - 1) {
                alpha[s * B + lane] = al;
                run += al;
            }
        }
    }
    run = fminf(fmaxf(run, 0.f), 1.f);
    alpha[(S - 1) * B + lane] = 1.f - run;
}

// ---------------------------------------------------------------------------
// Kernel 5: context partials. Grid (SCH s-chunks, B). Each block streams its
//   128 s-slices of enc[s,b,:] (4 KB coalesced each) -> deterministic partial.
// ---------------------------------------------------------------------------
__global__ void k_ctx(const float* __restrict__ enc,
                      const float* __restrict__ alpha) {
    const int sc = blockIdx.x;
    const int b = blockIdx.y;
    const int tid = threadIdx.x;
    const int s0 = sc * (S / SCH);
    float4 acc = make_float4(0.f, 0.f, 0.f, 0.f);
#pragma unroll 4
    for (int s = s0; s < s0 + S / SCH; s++) {
        const float al = __ldg(&alpha[s * B + b]);
        const float4 h = *(const float4*)(enc + ((size_t)(s * B + b)) * E + tid * 4);
        acc.x += al * h.x;  acc.y += al * h.y;
        acc.z += al * h.z;  acc.w += al * h.w;
    }
    *(float4*)&g_ctx[((size_t)(sc * B + b)) * E + tid * 4] = acc;
}

// ---------------------------------------------------------------------------
// Kernel 6: reduce the 16 context partials -> weighted_context.
// ---------------------------------------------------------------------------
__global__ void k_ctxred(float* __restrict__ out) {
    const int i = blockIdx.x * 256 + threadIdx.x;
    if (i >= B * E) return;
    float s = 0.f;
#pragma unroll
    for (int c = 0; c < SCH; c++) s += g_ctx[(size_t)c * B * E + i];
    out[i] = s;
}

// ---------------------------------------------------------------------------
extern "C" void kernel_launch(void* const* d_in, const int* in_sizes, int n_in,
                              void* d_out, int out_size) {
    const float* dec   = (const float*)d_in[0];   // [B, D]
    const float* enc   = (const float*)d_in[1];   // [S, B, E]
    const float* noise = (const float*)d_in[2];   // [S, B]
    const float* Wdec  = (const float*)d_in[3];   // [D, A]
    const float* Wenc  = (const float*)d_in[4];   // [E, A]
    const float* bias  = (const float*)d_in[5];   // [A]
    const float* v     = (const float*)d_in[6];   // [A]

    float* out       = (float*)d_out;             // [B*E] weighted_context
    float* alpha_out = out + B * E;               // [S*B] alpha

    k_decproj<<<B, 256>>>(dec, Wdec, bias);

    dim3 gg(NT, R / 128);
    k_gemm_energy<<<gg, 256>>>(enc, Wenc, v);

    k_p<<<R / 256, 256>>>(noise);

    k_scan<<<1, 32>>>(alpha_out);

    dim3 gc(SCH, B);
    k_ctx<<<gc, 256>>>(enc, alpha_out);

    k_ctxred<<<(B * E) / 256, 256>>>(out);
}

// round 7
// speedup vs baseline: 1.8018x; 1.8016x over previous
#include <cuda_runtime.h>
#include <cstdint>
#include <math.h>

static constexpr int S = 2048;
static constexpr int B = 32;
static constexpr int E = 1024;
static constexpr int A = 1024;
static constexpr int D = 1024;
static constexpr int R = S * B;

static constexpr int BM = 128, BN = 128, BK = 16;
static constexpr int NPASS  = A / BN;   // 8
static constexpr int CHUNKS = E / BK;   // 64
static constexpr int SCH = 16;

// ---- smem layout (floats), pad 132 keeps frag reads <=2-way ----
static constexpr int P = 132;
static constexpr int STG = BK * P;              // 2112 per stage
static constexpr int OFF_AS  = 0;               // [2][16][132]
static constexpr int OFF_BS  = 2 * STG;         // 4224
static constexpr int OFF_SZ  = OFF_BS + 2 * STG;// 8448  [32][132]
static constexpr int OFF_SV  = OFF_SZ + 32 * P; // 12672 [128]
static constexpr int OFF_RED = OFF_SV + BN;     // 12800 [128][2]
static constexpr int SMEM_F  = OFF_RED + BM * 2;// 13056
static constexpr int SMEM_BYTES = SMEM_F * 4;   // 52224

__device__ float g_z0[B * A];
__device__ float g_p[R];
__device__ float g_ctx[SCH * B * E];

__device__ __forceinline__ uint32_t cvt_tf32(float x) {
    uint32_t u;
    asm("cvt.rna.tf32.f32 %0, %1;" : "=r"(u) : "f"(x));
    return u;
}

__device__ __forceinline__ float fast_tanh(float x) {
    float e, r;
    asm("ex2.approx.f32 %0, %1;" : "=f"(e) : "f"(x * 2.885390082f)); // 2*log2(e)
    asm("rcp.approx.f32 %0, %1;" : "=f"(r) : "f"(e + 1.f));
    return fmaf(-2.f, r, 1.f);
}

// ---------------- Kernel 1: z0 = dec @ Wdec + bias ----------------
__global__ void k_decproj(const float* __restrict__ dec,
                          const float* __restrict__ Wdec,
                          const float* __restrict__ bias) {
    __shared__ float sd[D];
    const int b = blockIdx.x;
    const int tid = threadIdx.x;
    for (int i = tid; i < D; i += 256) sd[i] = dec[b * D + i];
    __syncthreads();
    float a0 = 0.f, a1 = 0.f, a2 = 0.f, a3 = 0.f;
#pragma unroll 4
    for (int e = 0; e < D; e++) {
        const float dv = sd[e];
        const float* w = Wdec + (size_t)e * A + tid;
        a0 += dv * w[0];   a1 += dv * w[256];
        a2 += dv * w[512]; a3 += dv * w[768];
    }
    g_z0[b * A + tid + 0]   = a0 + bias[tid + 0];
    g_z0[b * A + tid + 256] = a1 + bias[tid + 256];
    g_z0[b * A + tid + 512] = a2 + bias[tid + 512];
    g_z0[b * A + tid + 768] = a3 + bias[tid + 768];
}

// ---------------- Kernel 2: tf32 mma.sync energy -> p ----------------
// Per CTA: 128 rows, loops 8 N-tiles x (K pipeline). Emits p = sigmoid(e+noise).
__global__ __launch_bounds__(256, 2)
void k_energy(const float* __restrict__ enc,
              const float* __restrict__ Wenc,
              const float* __restrict__ v,
              const float* __restrict__ noise) {
    extern __shared__ float sm[];
    float* sz   = sm + OFF_SZ;
    float* sv   = sm + OFF_SV;
    float* sred = sm + OFF_RED;

    const int tid = threadIdx.x;
    const int lane = tid & 31, w = tid >> 5;
    const int wm = w >> 1, wn = w & 1;        // 4 x 2 warp grid
    const int qr = lane >> 2, qc = lane & 3;  // frag coords
    const int r0 = blockIdx.x * BM;

    // A-loader coords: o = i*256+tid -> row=o>>2 (0..127), cq=o&3
    // B-loader coords: o = i*256+tid -> kk=o>>5 (0..15), nq=o&31
    const int a_row0 = tid >> 2,  a_cq = tid & 3;
    const int b_kk0  = tid >> 5,  b_nq = tid & 31;

    float ereg[4] = {0.f, 0.f, 0.f, 0.f};     // (mt, half) row-energy partials

    for (int np = 0; np < NPASS; np++) {
        const int n0 = np * BN;

        // stage z0 tile [32][132-pad] + v tile
        for (int i = tid; i < 32 * (BN / 4); i += 256) {
            const int row = i >> 5, c4 = i & 31;
            const float4 f = *(const float4*)&g_z0[row * A + n0 + c4 * 4];
            *(float4*)&sz[row * P + c4 * 4] = f;
        }
        if (tid < BN / 4) *(float4*)&sv[tid * 4] = *(const float4*)&v[n0 + tid * 4];

        float c[2][8][4];
#pragma unroll
        for (int mt = 0; mt < 2; mt++)
#pragma unroll
            for (int nt = 0; nt < 8; nt++)
#pragma unroll
                for (int q = 0; q < 4; q++) c[mt][nt][q] = 0.f;

        float4 la[2], lb[2];
        // prologue: load + stage chunk 0
#pragma unroll
        for (int i = 0; i < 2; i++) {
            la[i] = *(const float4*)&enc[(size_t)(r0 + a_row0 + i * 64) * E + a_cq * 4];
            lb[i] = *(const float4*)&Wenc[(size_t)(b_kk0 + i * 8) * A + n0 + b_nq * 4];
        }
#pragma unroll
        for (int i = 0; i < 2; i++) {
            const int row = a_row0 + i * 64;
            float* as = sm + OFF_AS;
            as[(a_cq * 4 + 0) * P + row] = __uint_as_float(cvt_tf32(la[i].x));
            as[(a_cq * 4 + 1) * P + row] = __uint_as_float(cvt_tf32(la[i].y));
            as[(a_cq * 4 + 2) * P + row] = __uint_as_float(cvt_tf32(la[i].z));
            as[(a_cq * 4 + 3) * P + row] = __uint_as_float(cvt_tf32(la[i].w));
            float* bs = sm + OFF_BS + (b_kk0 + i * 8) * P + b_nq * 4;
            float4 cf;
            cf.x = __uint_as_float(cvt_tf32(lb[i].x));
            cf.y = __uint_as_float(cvt_tf32(lb[i].y));
            cf.z = __uint_as_float(cvt_tf32(lb[i].z));
            cf.w = __uint_as_float(cvt_tf32(lb[i].w));
            *(float4*)bs = cf;
        }
        __syncthreads();

        for (int ch = 0; ch < CHUNKS; ch++) {
            const int st = ch & 1;
            if (ch + 1 < CHUNKS) {
                const int k0 = (ch + 1) * BK;
#pragma unroll
                for (int i = 0; i < 2; i++) {
                    la[i] = *(const float4*)&enc[(size_t)(r0 + a_row0 + i * 64) * E + k0 + a_cq * 4];
                    lb[i] = *(const float4*)&Wenc[(size_t)(k0 + b_kk0 + i * 8) * A + n0 + b_nq * 4];
                }
            }

            const float* as = sm + OFF_AS + st * STG;
            const float* bs = sm + OFF_BS + st * STG;
#pragma unroll
            for (int ks = 0; ks < 2; ks++) {
                const int kk = ks * 8;
                uint32_t af[2][4], bf[8][2];
#pragma unroll
                for (int mt = 0; mt < 2; mt++) {
                    const int m = wm * 32 + mt * 16 + qr;
                    af[mt][0] = __float_as_uint(as[(kk + qc) * P + m]);
                    af[mt][1] = __float_as_uint(as[(kk + qc) * P + m + 8]);
                    af[mt][2] = __float_as_uint(as[(kk + qc + 4) * P + m]);
                    af[mt][3] = __float_as_uint(as[(kk + qc + 4) * P + m + 8]);
                }
#pragma unroll
                for (int nt = 0; nt < 8; nt++) {
                    const int n = wn * 64 + nt * 8 + qr;
                    bf[nt][0] = __float_as_uint(bs[(kk + qc) * P + n]);
                    bf[nt][1] = __float_as_uint(bs[(kk + qc + 4) * P + n]);
                }
#pragma unroll
                for (int mt = 0; mt < 2; mt++)
#pragma unroll
                    for (int nt = 0; nt < 8; nt++) {
                        asm volatile(
                            "mma.sync.aligned.m16n8k8.row.col.f32.tf32.tf32.f32 "
                            "{%0,%1,%2,%3}, {%4,%5,%6,%7}, {%8,%9}, {%0,%1,%2,%3};"
                            : "+f"(c[mt][nt][0]), "+f"(c[mt][nt][1]),
                              "+f"(c[mt][nt][2]), "+f"(c[mt][nt][3])
                            : "r"(af[mt][0]), "r"(af[mt][1]),
                              "r"(af[mt][2]), "r"(af[mt][3]),
                              "r"(bf[nt][0]), "r"(bf[nt][1]));
                    }
            }

            if (ch + 1 < CHUNKS) {
                const int st2 = (ch + 1) & 1;
                float* as2 = sm + OFF_AS + st2 * STG;
                float* bs2 = sm + OFF_BS + st2 * STG;
#pragma unroll
                for (int i = 0; i < 2; i++) {
                    const int row = a_row0 + i * 64;
                    as2[(a_cq * 4 + 0) * P + row] = __uint_as_float(cvt_tf32(la[i].x));
                    as2[(a_cq * 4 + 1) * P + row] = __uint_as_float(cvt_tf32(la[i].y));
                    as2[(a_cq * 4 + 2) * P + row] = __uint_as_float(cvt_tf32(la[i].z));
                    as2[(a_cq * 4 + 3) * P + row] = __uint_as_float(cvt_tf32(la[i].w));
                    float4 cf;
                    cf.x = __uint_as_float(cvt_tf32(lb[i].x));
                    cf.y = __uint_as_float(cvt_tf32(lb[i].y));
                    cf.z = __uint_as_float(cvt_tf32(lb[i].z));
                    cf.w = __uint_as_float(cvt_tf32(lb[i].w));
                    *(float4*)(bs2 + (b_kk0 + i * 8) * P + b_nq * 4) = cf;
                }
            }
            __syncthreads();
        }

        // epilogue for this N-pass: +z0, tanh, dot v, accumulate per-row
#pragma unroll
        for (int mt = 0; mt < 2; mt++)
#pragma unroll
            for (int half = 0; half < 2; half++) {
                const int bz = (mt * 16 + half * 8 + qr) & 31;
                float acc = 0.f;
#pragma unroll
                for (int nt = 0; nt < 8; nt++) {
                    const int lc = wn * 64 + nt * 8 + 2 * qc;
                    const float x0 = c[mt][nt][half * 2 + 0] + sz[bz * P + lc];
                    const float x1 = c[mt][nt][half * 2 + 1] + sz[bz * P + lc + 1];
                    acc = fmaf(sv[lc],     fast_tanh(x0), acc);
                    acc = fmaf(sv[lc + 1], fast_tanh(x1), acc);
                }
                ereg[mt * 2 + half] += acc;
            }
        __syncthreads();   // sz/sv reused next pass
    }

    // quad reduce (lanes sharing a row differ only in qc = lane bits 0-1)
#pragma unroll
    for (int q = 0; q < 4; q++) {
        ereg[q] += __shfl_xor_sync(0xFFFFFFFFu, ereg[q], 1);
        ereg[q] += __shfl_xor_sync(0xFFFFFFFFu, ereg[q], 2);
    }
    if (qc == 0) {
#pragma unroll
        for (int mt = 0; mt < 2; mt++)
#pragma unroll
            for (int half = 0; half < 2; half++) {
                const int row = wm * 32 + mt * 16 + half * 8 + qr;
                sred[row * 2 + wn] = ereg[mt * 2 + half];
            }
    }
    __syncthreads();
    if (tid < BM) {
        const float e = sred[tid * 2] + sred[tid * 2 + 1];
        const float x = e + noise[r0 + tid];
        g_p[r0 + tid] = 1.f / (1.f + expf(-x));
    }
}

// ---------------- Kernel 3: parallel monotonic scan ----------------
__global__ void k_scan(float* __restrict__ alpha) {
    __shared__ float segprod[32][33];
    __shared__ float segsum[32][33];
    const int tid = threadIdx.x;
    const int b = tid & 31, seg = tid >> 5;
    const int SL = S / 32;                 // 64
    const int s0 = seg * SL;

    float prod = 1.f;
    for (int i0 = 0; i0 < SL; i0 += 8) {
        float t[8];
#pragma unroll
        for (int i = 0; i < 8; i++) t[i] = g_p[(s0 + i0 + i) * B + b];
#pragma unroll
        for (int i = 0; i < 8; i++) prod *= (1.f - t[i]);
    }
    segprod[seg][b] = prod;
    __syncthreads();

    float cp = 1.f;
    for (int s = 0; s < seg; s++) cp *= segprod[s][b];

    float run = 0.f;
    for (int i0 = 0; i0 < SL; i0 += 8) {
        float t[8];
#pragma unroll
        for (int i = 0; i < 8; i++) t[i] = g_p[(s0 + i0 + i) * B + b];
#pragma unroll
        for (int i = 0; i < 8; i++) {
            const int s = s0 + i0 + i;
            const float al = t[i] * cp;
            cp *= (1.f - t[i]);
            alpha[s * B + b] = al;
            if (s < S - 1) run += al;
        }
    }
    segsum[seg][b] = run;
    __syncthreads();

    if (tid < 32) {
        float tot = 0.f;
#pragma unroll
        for (int s = 0; s < 32; s++) tot += segsum[s][tid];
        tot = fminf(fmaxf(tot, 0.f), 1.f);
        alpha[(S - 1) * B + tid] = 1.f - tot;
    }
}

// ---------------- Kernel 4: context partials ----------------
__global__ void k_ctx(const float* __restrict__ enc,
                      const float* __restrict__ alpha) {
    const int sc = blockIdx.x;
    const int b = blockIdx.y;
    const int tid = threadIdx.x;
    const int s0 = sc * (S / SCH);
    float4 acc = make_float4(0.f, 0.f, 0.f, 0.f);
#pragma unroll 4
    for (int s = s0; s < s0 + S / SCH; s++) {
        const float al = __ldg(&alpha[s * B + b]);
        const float4 hh = *(const float4*)(enc + ((size_t)(s * B + b)) * E + tid * 4);
        acc.x += al * hh.x;  acc.y += al * hh.y;
        acc.z += al * hh.z;  acc.w += al * hh.w;
    }
    *(float4*)&g_ctx[((size_t)(sc * B + b)) * E + tid * 4] = acc;
}

// ---------------- Kernel 5: reduce context partials ----------------
__global__ void k_ctxred(float* __restrict__ out) {
    const int i = blockIdx.x * 256 + threadIdx.x;
    if (i >= B * E) return;
    float s = 0.f;
#pragma unroll
    for (int c = 0; c < SCH; c++) s += g_ctx[(size_t)c * B * E + i];
    out[i] = s;
}

// ---------------------------------------------------------------------------
extern "C" void kernel_launch(void* const* d_in, const int* in_sizes, int n_in,
                              void* d_out, int out_size) {
    const float* dec   = (const float*)d_in[0];
    const float* enc   = (const float*)d_in[1];
    const float* noise = (const float*)d_in[2];
    const float* Wdec  = (const float*)d_in[3];
    const float* Wenc  = (const float*)d_in[4];
    const float* bias  = (const float*)d_in[5];
    const float* v     = (const float*)d_in[6];

    float* out       = (float*)d_out;             // [B*E] weighted_context
    float* alpha_out = out + B * E;               // [S*B] alpha

    cudaFuncSetAttribute(k_energy, cudaFuncAttributeMaxDynamicSharedMemorySize,
                         SMEM_BYTES);

    k_decproj<<<B, 256>>>(dec, Wdec, bias);

    k_energy<<<R / BM, 256, SMEM_BYTES>>>(enc, Wenc, v, noise);

    k_scan<<<1, 1024>>>(alpha_out);

    dim3 gc(SCH, B);
    k_ctx<<<gc, 256>>>(enc, alpha_out);

    k_ctxred<<<(B * E) / 256, 256>>>(out);
}

// round 8
// speedup vs baseline: 3.7578x; 2.0856x over previous
#include <cuda_runtime.h>
#include <cuda_fp16.h>
#include <cstdint>
#include <math.h>

static constexpr int S = 2048;
static constexpr int B = 32;
static constexpr int E = 1024;
static constexpr int A = 1024;
static constexpr int D = 1024;
static constexpr int R = S * B;

static constexpr int BM = 128, BN = 128;
static constexpr int BKC = 64;            // k per chunk
static constexpr int CHUNKS = E / BKC;    // 16
static constexpr int NPASS = A / BN;      // 8
static constexpr int SCH = 16;

// smem byte offsets
static constexpr int SM_A   = 0;          // 2 stages x 16384 (128 rows x 128B)
static constexpr int SM_B   = 32768;      // 2 stages x 16384
static constexpr int SM_Z   = 65536;      // [32][132] f32 = 16896
static constexpr int SM_V   = 82432;      // 128 f32
static constexpr int SM_RED = 82944;      // 128x2 f32
static constexpr int SMEM_BYTES = 83968;

__device__ float g_z0[B * A];
__device__ float g_p[R];
__device__ float g_ctx[SCH * B * E];
__device__ __align__(16) __half g_encH[(size_t)R * E];    // 128 MB scratch
__device__ __align__(16) __half g_WencTH[(size_t)A * E];  // [a][e] fp16

__device__ __forceinline__ uint32_t smem_u32(const void* p) {
    uint32_t a;
    asm("{ .reg .u64 t; cvta.to.shared.u64 t, %1; cvt.u32.u64 %0, t; }"
        : "=r"(a) : "l"(p));
    return a;
}

#define CP16(dst, src) \
    asm volatile("cp.async.cg.shared.global [%0], [%1], 16;" \
                 :: "r"(dst), "l"(src))
#define CP_COMMIT() asm volatile("cp.async.commit_group;" ::: "memory")
#define CP_WAIT1()  asm volatile("cp.async.wait_group 1;" ::: "memory")

#define LDMX4(r0, r1, r2, r3, addr) \
    asm volatile("ldmatrix.sync.aligned.m8n8.x4.shared.b16 {%0,%1,%2,%3}, [%4];" \
                 : "=r"(r0), "=r"(r1), "=r"(r2), "=r"(r3) : "r"(addr))

__device__ __forceinline__ float fast_tanh(float x) {
    float e, r;
    asm("ex2.approx.f32 %0, %1;" : "=f"(e) : "f"(x * 2.885390082f));
    asm("rcp.approx.f32 %0, %1;" : "=f"(r) : "f"(e + 1.f));
    return fmaf(-2.f, r, 1.f);
}

// ---------------- Kernel 0a: enc -> fp16 ----------------
__global__ void k_prep_enc(const float* __restrict__ enc) {
    const size_t i = ((size_t)blockIdx.x * 256 + threadIdx.x) * 8;
    const float4 f0 = *(const float4*)(enc + i);
    const float4 f1 = *(const float4*)(enc + i + 4);
    __half2 h[4];
    h[0] = __floats2half2_rn(f0.x, f0.y);
    h[1] = __floats2half2_rn(f0.z, f0.w);
    h[2] = __floats2half2_rn(f1.x, f1.y);
    h[3] = __floats2half2_rn(f1.z, f1.w);
    *(uint4*)&g_encH[i] = *(uint4*)h;
}

// ---------------- Kernel 0b: WencTH[a][e] = (half)Wenc[e][a] ----------------
__global__ void k_prep_wt(const float* __restrict__ Wenc) {
    __shared__ float t[32][33];
    const int bx = blockIdx.x * 32;   // a
    const int by = blockIdx.y * 32;   // e
    const int x = threadIdx.x, y = threadIdx.y;
#pragma unroll
    for (int i = 0; i < 32; i += 8)
        t[y + i][x] = Wenc[(size_t)(by + y + i) * A + bx + x];
    __syncthreads();
#pragma unroll
    for (int i = 0; i < 32; i += 8)
        g_WencTH[(size_t)(bx + y + i) * E + by + x] = __float2half_rn(t[x][y + i]);
}

// ---------------- Kernel 1: z0 = dec @ Wdec + bias (fp32) ----------------
__global__ void k_decproj(const float* __restrict__ dec,
                          const float* __restrict__ Wdec,
                          const float* __restrict__ bias) {
    __shared__ float sd[D];
    const int b = blockIdx.x;
    const int tid = threadIdx.x;
    for (int i = tid; i < D; i += 256) sd[i] = dec[b * D + i];
    __syncthreads();
    float a0 = 0.f, a1 = 0.f, a2 = 0.f, a3 = 0.f;
#pragma unroll 4
    for (int e = 0; e < D; e++) {
        const float dv = sd[e];
        const float* w = Wdec + (size_t)e * A + tid;
        a0 += dv * w[0];   a1 += dv * w[256];
        a2 += dv * w[512]; a3 += dv * w[768];
    }
    g_z0[b * A + tid + 0]   = a0 + bias[tid + 0];
    g_z0[b * A + tid + 256] = a1 + bias[tid + 256];
    g_z0[b * A + tid + 512] = a2 + bias[tid + 512];
    g_z0[b * A + tid + 768] = a3 + bias[tid + 768];
}

// ---------------- Kernel 2: fp16 mma energy -> p ----------------
__global__ __launch_bounds__(256, 2)
void k_energy(const float* __restrict__ v, const float* __restrict__ noise) {
    extern __shared__ __align__(1024) char smem[];
    const uint32_t sb = smem_u32(smem);
    float* sz   = (float*)(smem + SM_Z);
    float* sv   = (float*)(smem + SM_V);
    float* sred = (float*)(smem + SM_RED);

    const int tid = threadIdx.x;
    const int lane = tid & 31, w = tid >> 5;
    const int wm = w >> 1, wn = w & 1;        // 4 x 2 warp grid
    const int qr = lane >> 2, qc = lane & 3;
    const int r0 = blockIdx.x * BM;

    // ldmatrix lane geometry
    const int t8 = lane >> 3, rr = lane & 7;
    const int ctA = t8 >> 1;                  // k-chunk select for A
    const int ctB = t8 & 1;                   // k-chunk select for B
    int mrowA[2], nrowB[4];
#pragma unroll
    for (int mt = 0; mt < 2; mt++) mrowA[mt] = wm * 32 + mt * 16 + (t8 & 1) * 8 + rr;
#pragma unroll
    for (int np = 0; np < 4; np++) nrowB[np] = wn * 64 + np * 16 + (t8 >> 1) * 8 + rr;

    // cp.async loader geometry: each thread: row = tid>>1, 4 chunks of 16B
    const int lm = tid >> 1;
    const int cb = (tid & 1) * 4;
    const int lm7 = lm & 7;

    float ereg[4] = {0.f, 0.f, 0.f, 0.f};

    for (int np = 0; np < NPASS; np++) {
        const int n0 = np * BN;

        // stage z0 [32][132] + v
        for (int i = tid; i < 32 * 32; i += 256) {
            const int row = i >> 5, c4 = i & 31;
            const float4 f = *(const float4*)&g_z0[row * A + n0 + c4 * 4];
            *(float4*)&sz[row * 132 + c4 * 4] = f;
        }
        if (tid < 32) *(float4*)&sv[tid * 4] = *(const float4*)&v[n0 + tid * 4];

        float c[2][8][4];
#pragma unroll
        for (int mt = 0; mt < 2; mt++)
#pragma unroll
            for (int nt = 0; nt < 8; nt++)
#pragma unroll
                for (int q = 0; q < 4; q++) c[mt][nt][q] = 0.f;

        // prologue: chunks 0,1
#pragma unroll
        for (int pc = 0; pc < 2; pc++) {
            const __half* srcA = g_encH + (size_t)(r0 + lm) * E + pc * BKC + cb * 8;
            const __half* srcB = g_WencTH + (size_t)(n0 + lm) * E + pc * BKC + cb * 8;
            const uint32_t dA = sb + SM_A + pc * 16384 + lm * 128;
            const uint32_t dB = sb + SM_B + pc * 16384 + lm * 128;
#pragma unroll
            for (int j = 0; j < 4; j++) {
                const int cc = cb + j;
                CP16(dA + ((cc ^ lm7) * 16), srcA + j * 8);
                CP16(dB + ((cc ^ lm7) * 16), srcB + j * 8);
            }
            CP_COMMIT();
        }

        for (int ch = 0; ch < CHUNKS; ch++) {
            const int st = ch & 1;
            CP_WAIT1();
            __syncthreads();

            const uint32_t aB = sb + SM_A + st * 16384;
            const uint32_t bB = sb + SM_B + st * 16384;
#pragma unroll
            for (int ks = 0; ks < 4; ks++) {
                uint32_t af[2][4], bf[8][2];
#pragma unroll
                for (int mt = 0; mt < 2; mt++) {
                    const int cc = ks * 2 + ctA;
                    const uint32_t addr =
                        aB + mrowA[mt] * 128 + ((cc ^ (mrowA[mt] & 7)) * 16);
                    LDMX4(af[mt][0], af[mt][1], af[mt][2], af[mt][3], addr);
                }
#pragma unroll
                for (int ntp = 0; ntp < 4; ntp++) {
                    const int cc = ks * 2 + ctB;
                    const uint32_t addr =
                        bB + nrowB[ntp] * 128 + ((cc ^ (nrowB[ntp] & 7)) * 16);
                    LDMX4(bf[2 * ntp][0], bf[2 * ntp][1],
                          bf[2 * ntp + 1][0], bf[2 * ntp + 1][1], addr);
                }
#pragma unroll
                for (int mt = 0; mt < 2; mt++)
#pragma unroll
                    for (int nt = 0; nt < 8; nt++) {
                        asm volatile(
                            "mma.sync.aligned.m16n8k16.row.col.f32.f16.f16.f32 "
                            "{%0,%1,%2,%3}, {%4,%5,%6,%7}, {%8,%9}, {%0,%1,%2,%3};"
                            : "+f"(c[mt][nt][0]), "+f"(c[mt][nt][1]),
                              "+f"(c[mt][nt][2]), "+f"(c[mt][nt][3])
                            : "r"(af[mt][0]), "r"(af[mt][1]),
                              "r"(af[mt][2]), "r"(af[mt][3]),
                              "r"(bf[nt][0]), "r"(bf[nt][1]));
                    }
            }
            __syncthreads();

            if (ch + 2 < CHUNKS) {
                const int nc = ch + 2;
                const __half* srcA = g_encH + (size_t)(r0 + lm) * E + nc * BKC + cb * 8;
                const __half* srcB = g_WencTH + (size_t)(n0 + lm) * E + nc * BKC + cb * 8;
                const uint32_t dA = sb + SM_A + st * 16384 + lm * 128;
                const uint32_t dB = sb + SM_B + st * 16384 + lm * 128;
#pragma unroll
                for (int j = 0; j < 4; j++) {
                    const int cc = cb + j;
                    CP16(dA + ((cc ^ lm7) * 16), srcA + j * 8);
                    CP16(dB + ((cc ^ lm7) * 16), srcB + j * 8);
                }
            }
            CP_COMMIT();
        }

        // epilogue: +z0, tanh, dot v
#pragma unroll
        for (int mt = 0; mt < 2; mt++)
#pragma unroll
            for (int half = 0; half < 2; half++) {
                const int bz = (mt * 16 + half * 8 + qr) & 31;
                float acc = 0.f;
#pragma unroll
                for (int nt = 0; nt < 8; nt++) {
                    const int lc = wn * 64 + nt * 8 + 2 * qc;
                    const float x0 = c[mt][nt][half * 2 + 0] + sz[bz * 132 + lc];
                    const float x1 = c[mt][nt][half * 2 + 1] + sz[bz * 132 + lc + 1];
                    acc = fmaf(sv[lc],     fast_tanh(x0), acc);
                    acc = fmaf(sv[lc + 1], fast_tanh(x1), acc);
                }
                ereg[mt * 2 + half] += acc;
            }
        __syncthreads();
    }

    // quad reduce across qc
#pragma unroll
    for (int q = 0; q < 4; q++) {
        ereg[q] += __shfl_xor_sync(0xFFFFFFFFu, ereg[q], 1);
        ereg[q] += __shfl_xor_sync(0xFFFFFFFFu, ereg[q], 2);
    }
    if (qc == 0) {
#pragma unroll
        for (int mt = 0; mt < 2; mt++)
#pragma unroll
            for (int half = 0; half < 2; half++) {
                const int row = wm * 32 + mt * 16 + half * 8 + qr;
                sred[row * 2 + wn] = ereg[mt * 2 + half];
            }
    }
    __syncthreads();
    if (tid < BM) {
        const float e = sred[tid * 2] + sred[tid * 2 + 1];
        const float x = e + noise[r0 + tid];
        g_p[r0 + tid] = 1.f / (1.f + expf(-x));
    }
}

// ---------------- Kernel 3: parallel monotonic scan ----------------
__global__ void k_scan(float* __restrict__ alpha) {
    __shared__ float segprod[32][33];
    __shared__ float segsum[32][33];
    const int tid = threadIdx.x;
    const int b = tid & 31, seg = tid >> 5;
    const int SL = S / 32;
    const int s0 = seg * SL;

    float prod = 1.f;
    for (int i0 = 0; i0 < SL; i0 += 8) {
        float t[8];
#pragma unroll
        for (int i = 0; i < 8; i++) t[i] = g_p[(s0 + i0 + i) * B + b];
#pragma unroll
        for (int i = 0; i < 8; i++) prod *= (1.f - t[i]);
    }
    segprod[seg][b] = prod;
    __syncthreads();

    float cp = 1.f;
    for (int s = 0; s < seg; s++) cp *= segprod[s][b];

    float run = 0.f;
    for (int i0 = 0; i0 < SL; i0 += 8) {
        float t[8];
#pragma unroll
        for (int i = 0; i < 8; i++) t[i] = g_p[(s0 + i0 + i) * B + b];
#pragma unroll
        for (int i = 0; i < 8; i++) {
            const int s = s0 + i0 + i;
            const float al = t[i] * cp;
            cp *= (1.f - t[i]);
            alpha[s * B + b] = al;
            if (s < S - 1) run += al;
        }
    }
    segsum[seg][b] = run;
    __syncthreads();

    if (tid < 32) {
        float tot = 0.f;
#pragma unroll
        for (int s = 0; s < 32; s++) tot += segsum[s][tid];
        tot = fminf(fmaxf(tot, 0.f), 1.f);
        alpha[(S - 1) * B + tid] = 1.f - tot;
    }
}

// ---------------- Kernel 4: context partials ----------------
__global__ void k_ctx(const float* __restrict__ enc,
                      const float* __restrict__ alpha) {
    const int sc = blockIdx.x;
    const int b = blockIdx.y;
    const int tid = threadIdx.x;
    const int s0 = sc * (S / SCH);
    float4 acc = make_float4(0.f, 0.f, 0.f, 0.f);
#pragma unroll 4
    for (int s = s0; s < s0 + S / SCH; s++) {
        const float al = __ldg(&alpha[s * B + b]);
        const float4 hh = *(const float4*)(enc + ((size_t)(s * B + b)) * E + tid * 4);
        acc.x += al * hh.x;  acc.y += al * hh.y;
        acc.z += al * hh.z;  acc.w += al * hh.w;
    }
    *(float4*)&g_ctx[((size_t)(sc * B + b)) * E + tid * 4] = acc;
}

// ---------------- Kernel 5: reduce context partials ----------------
__global__ void k_ctxred(float* __restrict__ out) {
    const int i = blockIdx.x * 256 + threadIdx.x;
    if (i >= B * E) return;
    float s = 0.f;
#pragma unroll
    for (int c = 0; c < SCH; c++) s += g_ctx[(size_t)c * B * E + i];
    out[i] = s;
}

// ---------------------------------------------------------------------------
extern "C" void kernel_launch(void* const* d_in, const int* in_sizes, int n_in,
                              void* d_out, int out_size) {
    const float* dec   = (const float*)d_in[0];
    const float* enc   = (const float*)d_in[1];
    const float* noise = (const float*)d_in[2];
    const float* Wdec  = (const float*)d_in[3];
    const float* Wenc  = (const float*)d_in[4];
    const float* bias  = (const float*)d_in[5];
    const float* v     = (const float*)d_in[6];

    float* out       = (float*)d_out;             // [B*E] weighted_context
    float* alpha_out = out + B * E;               // [S*B] alpha

    cudaFuncSetAttribute(k_energy, cudaFuncAttributeMaxDynamicSharedMemorySize,
                         SMEM_BYTES);

    k_prep_enc<<<(int)(((size_t)R * E) / 2048), 256>>>(enc);
    k_prep_wt<<<dim3(A / 32, E / 32), dim3(32, 8)>>>(Wenc);
    k_decproj<<<B, 256>>>(dec, Wdec, bias);

    k_energy<<<R / BM, 256, SMEM_BYTES>>>(v, noise);

    k_scan<<<1, 1024>>>(alpha_out);

    dim3 gc(SCH, B);
    k_ctx<<<gc, 256>>>(enc, alpha_out);

    k_ctxred<<<(B * E) / 256, 256>>>(out);
}

// round 9
// speedup vs baseline: 4.7118x; 1.2539x over previous
#include <cuda_runtime.h>
#include <cuda_fp16.h>
#include <cstdint>
#include <math.h>

static constexpr int S = 2048;
static constexpr int B = 32;
static constexpr int E = 1024;
static constexpr int A = 1024;
static constexpr int D = 1024;
static constexpr int R = S * B;

static constexpr int BM = 128, BN = 128;
static constexpr int BKC = 64;            // k per chunk
static constexpr int CHUNKS = E / BKC;    // 16
static constexpr int NPASS = A / BN;      // 8
static constexpr int GTOT = NPASS * CHUNKS; // 128 global chunks
static constexpr int SCH = 16;

// smem byte offsets: 3 stages x (16KB A + 16KB B) + reduction
static constexpr int SM_A   = 0;          // 3 x 16384
static constexpr int SM_B   = 49152;      // 3 x 16384
static constexpr int SM_RED = 98304;      // 128x2 f32
static constexpr int SMEM_BYTES = 99328;

__device__ float g_z0[B * A];
__device__ float g_zpart[8][B * A];
__device__ float g_p[R];
__device__ float g_ctx[SCH * B * E];
__device__ __align__(16) __half g_encH[(size_t)R * E];    // 128 MB scratch
__device__ __align__(16) __half g_WencTH[(size_t)A * E];  // [a][e] fp16

__device__ __forceinline__ uint32_t smem_u32(const void* p) {
    uint32_t a;
    asm("{ .reg .u64 t; cvta.to.shared.u64 t, %1; cvt.u32.u64 %0, t; }"
        : "=r"(a) : "l"(p));
    return a;
}

#define CP16(dst, src) \
    asm volatile("cp.async.cg.shared.global [%0], [%1], 16;" \
                 :: "r"(dst), "l"(src))
#define CP_COMMIT() asm volatile("cp.async.commit_group;" ::: "memory")
#define CP_WAIT1()  asm volatile("cp.async.wait_group 1;" ::: "memory")

#define LDMX4(r0, r1, r2, r3, addr) \
    asm volatile("ldmatrix.sync.aligned.m8n8.x4.shared.b16 {%0,%1,%2,%3}, [%4];" \
                 : "=r"(r0), "=r"(r1), "=r"(r2), "=r"(r3) : "r"(addr))

__device__ __forceinline__ float fast_tanh(float x) {
    float e, r;
    asm("ex2.approx.f32 %0, %1;" : "=f"(e) : "f"(x * 2.885390082f));
    asm("rcp.approx.f32 %0, %1;" : "=f"(r) : "f"(e + 1.f));
    return fmaf(-2.f, r, 1.f);
}

// ---------------- Kernel 0a: enc -> fp16 ----------------
__global__ void k_prep_enc(const float* __restrict__ enc) {
    const size_t i = ((size_t)blockIdx.x * 256 + threadIdx.x) * 8;
    const float4 f0 = *(const float4*)(enc + i);
    const float4 f1 = *(const float4*)(enc + i + 4);
    __half2 h[4];
    h[0] = __floats2half2_rn(f0.x, f0.y);
    h[1] = __floats2half2_rn(f0.z, f0.w);
    h[2] = __floats2half2_rn(f1.x, f1.y);
    h[3] = __floats2half2_rn(f1.z, f1.w);
    *(uint4*)&g_encH[i] = *(uint4*)h;
}

// ---------------- Kernel 0b: WencTH[a][e] = (half)Wenc[e][a] ----------------
__global__ void k_prep_wt(const float* __restrict__ Wenc) {
    __shared__ float t[32][33];
    const int bx = blockIdx.x * 32;   // a
    const int by = blockIdx.y * 32;   // e
    const int x = threadIdx.x, y = threadIdx.y;
#pragma unroll
    for (int i = 0; i < 32; i += 8)
        t[y + i][x] = Wenc[(size_t)(by + y + i) * A + bx + x];
    __syncthreads();
#pragma unroll
    for (int i = 0; i < 32; i += 8)
        g_WencTH[(size_t)(bx + y + i) * E + by + x] = __float2half_rn(t[x][y + i]);
}

// ---------------- Kernel 1a: z0 partials (K-split x8) ----------------
__global__ void k_decproj1(const float* __restrict__ dec,
                           const float* __restrict__ Wdec) {
    __shared__ float sd[128];
    const int b = blockIdx.x, ks = blockIdx.y;
    const int tid = threadIdx.x;
    if (tid < 128) sd[tid] = dec[b * D + ks * 128 + tid];
    __syncthreads();
    float a0 = 0.f, a1 = 0.f, a2 = 0.f, a3 = 0.f;
#pragma unroll 4
    for (int e = 0; e < 128; e++) {
        const float dv = sd[e];
        const float* w = Wdec + (size_t)(ks * 128 + e) * A + tid;
        a0 += dv * w[0];   a1 += dv * w[256];
        a2 += dv * w[512]; a3 += dv * w[768];
    }
    float* zp = g_zpart[ks] + b * A + tid;
    zp[0] = a0; zp[256] = a1; zp[512] = a2; zp[768] = a3;
}

// ---------------- Kernel 1b: z0 = sum partials + bias ----------------
__global__ void k_decproj2(const float* __restrict__ bias) {
    const int i = blockIdx.x * 256 + threadIdx.x;
    float s = bias[i & (A - 1)];
#pragma unroll
    for (int ks = 0; ks < 8; ks++) s += g_zpart[ks][i];
    g_z0[i] = s;
}

// ---------------- k_energy helpers ----------------
__device__ __forceinline__ void issue_stage(int g, int r0, int lm, int cb,
                                            int lm7, uint32_t sb) {
    const int np = g >> 4, ch = g & 15;
    const __half* srcA = g_encH + (size_t)(r0 + lm) * E + ch * BKC + cb * 8;
    const __half* srcB = g_WencTH + (size_t)(np * BN + lm) * E + ch * BKC + cb * 8;
    const uint32_t dA = sb + SM_A + (g % 3) * 16384 + lm * 128;
    const uint32_t dB = sb + SM_B + (g % 3) * 16384 + lm * 128;
#pragma unroll
    for (int j = 0; j < 4; j++) {
        const int cc = cb + j;
        CP16(dA + ((cc ^ lm7) * 16), srcA + j * 8);
        CP16(dB + ((cc ^ lm7) * 16), srcB + j * 8);
    }
}

// ---------------- Kernel 2: fp16 mma energy -> p ----------------
__global__ __launch_bounds__(256, 2)
void k_energy(const float* __restrict__ v, const float* __restrict__ noise) {
    extern __shared__ __align__(1024) char smem[];
    const uint32_t sb = smem_u32(smem);
    float* sred = (float*)(smem + SM_RED);

    const int tid = threadIdx.x;
    const int lane = tid & 31, w = tid >> 5;
    const int wm = w >> 1, wn = w & 1;        // 4 x 2 warp grid
    const int qr = lane >> 2, qc = lane & 3;
    const int r0 = blockIdx.x * BM;

    // ldmatrix lane geometry (validated in round 7)
    const int t8 = lane >> 3, rr = lane & 7;
    const int ctA = t8 >> 1;
    const int ctB = t8 & 1;
    int mrowA[2], nrowB[4];
#pragma unroll
    for (int mt = 0; mt < 2; mt++) mrowA[mt] = wm * 32 + mt * 16 + (t8 & 1) * 8 + rr;
#pragma unroll
    for (int np = 0; np < 4; np++) nrowB[np] = wn * 64 + np * 16 + (t8 >> 1) * 8 + rr;

    // cp.async loader geometry
    const int lm = tid >> 1;
    const int cb = (tid & 1) * 4;
    const int lm7 = lm & 7;

    float ereg[4] = {0.f, 0.f, 0.f, 0.f};
    float c[2][8][4];
#pragma unroll
    for (int mt = 0; mt < 2; mt++)
#pragma unroll
        for (int nt = 0; nt < 8; nt++)
#pragma unroll
            for (int q = 0; q < 4; q++) c[mt][nt][q] = 0.f;

    issue_stage(0, r0, lm, cb, lm7, sb); CP_COMMIT();
    issue_stage(1, r0, lm, cb, lm7, sb); CP_COMMIT();

#pragma unroll 1
    for (int g = 0; g < GTOT; g++) {
        CP_WAIT1();
        __syncthreads();

        const uint32_t aB = sb + SM_A + (g % 3) * 16384;
        const uint32_t bB = sb + SM_B + (g % 3) * 16384;
#pragma unroll
        for (int ks = 0; ks < 4; ks++) {
            uint32_t af[2][4], bf[8][2];
#pragma unroll
            for (int mt = 0; mt < 2; mt++) {
                const int cc = ks * 2 + ctA;
                const uint32_t addr =
                    aB + mrowA[mt] * 128 + ((cc ^ (mrowA[mt] & 7)) * 16);
                LDMX4(af[mt][0], af[mt][1], af[mt][2], af[mt][3], addr);
            }
#pragma unroll
            for (int ntp = 0; ntp < 4; ntp++) {
                const int cc = ks * 2 + ctB;
                const uint32_t addr =
                    bB + nrowB[ntp] * 128 + ((cc ^ (nrowB[ntp] & 7)) * 16);
                LDMX4(bf[2 * ntp][0], bf[2 * ntp][1],
                      bf[2 * ntp + 1][0], bf[2 * ntp + 1][1], addr);
            }
#pragma unroll
            for (int mt = 0; mt < 2; mt++)
#pragma unroll
                for (int nt = 0; nt < 8; nt++) {
                    asm volatile(
                        "mma.sync.aligned.m16n8k16.row.col.f32.f16.f16.f32 "
                        "{%0,%1,%2,%3}, {%4,%5,%6,%7}, {%8,%9}, {%0,%1,%2,%3};"
                        : "+f"(c[mt][nt][0]), "+f"(c[mt][nt][1]),
                          "+f"(c[mt][nt][2]), "+f"(c[mt][nt][3])
                        : "r"(af[mt][0]), "r"(af[mt][1]),
                          "r"(af[mt][2]), "r"(af[mt][3]),
                          "r"(bf[nt][0]), "r"(bf[nt][1]));
                }
        }

        if (g + 2 < GTOT) issue_stage(g + 2, r0, lm, cb, lm7, sb);
        CP_COMMIT();   // always commit so wait_group counting stays uniform

        if ((g & 15) == 15) {
            // epilogue for pass np = g>>4: +z0, tanh, dot v (z0/v from L2)
            const int n0 = (g >> 4) * BN;
#pragma unroll
            for (int mt = 0; mt < 2; mt++)
#pragma unroll
                for (int half = 0; half < 2; half++) {
                    const int bz = (mt * 16 + half * 8 + qr) & 31;
                    const float* zr = g_z0 + bz * A + n0;
                    float acc = 0.f;
#pragma unroll
                    for (int nt = 0; nt < 8; nt++) {
                        const int lc = wn * 64 + nt * 8 + 2 * qc;
                        const float x0 = c[mt][nt][half * 2 + 0] + __ldg(zr + lc);
                        const float x1 = c[mt][nt][half * 2 + 1] + __ldg(zr + lc + 1);
                        acc = fmaf(__ldg(&v[n0 + lc]),     fast_tanh(x0), acc);
                        acc = fmaf(__ldg(&v[n0 + lc + 1]), fast_tanh(x1), acc);
                    }
                    ereg[mt * 2 + half] += acc;
#pragma unroll
                    for (int nt = 0; nt < 8; nt++) {
                        c[mt][nt][half * 2 + 0] = 0.f;
                        c[mt][nt][half * 2 + 1] = 0.f;
                    }
                }
        }
    }

    // quad reduce across qc
#pragma unroll
    for (int q = 0; q < 4; q++) {
        ereg[q] += __shfl_xor_sync(0xFFFFFFFFu, ereg[q], 1);
        ereg[q] += __shfl_xor_sync(0xFFFFFFFFu, ereg[q], 2);
    }
    __syncthreads();
    if (qc == 0) {
#pragma unroll
        for (int mt = 0; mt < 2; mt++)
#pragma unroll
            for (int half = 0; half < 2; half++) {
                const int row = wm * 32 + mt * 16 + half * 8 + qr;
                sred[row * 2 + wn] = ereg[mt * 2 + half];
            }
    }
    __syncthreads();
    if (tid < BM) {
        const float e = sred[tid * 2] + sred[tid * 2 + 1];
        const float x = e + noise[r0 + tid];
        g_p[r0 + tid] = 1.f / (1.f + expf(-x));
    }
}

// ---------------- Kernel 3: parallel monotonic scan ----------------
__global__ void k_scan(float* __restrict__ alpha) {
    __shared__ float segprod[32][33];
    __shared__ float segsum[32][33];
    const int tid = threadIdx.x;
    const int b = tid & 31, seg = tid >> 5;
    const int SL = S / 32;
    const int s0 = seg * SL;

    float prod = 1.f;
    for (int i0 = 0; i0 < SL; i0 += 8) {
        float t[8];
#pragma unroll
        for (int i = 0; i < 8; i++) t[i] = g_p[(s0 + i0 + i) * B + b];
#pragma unroll
        for (int i = 0; i < 8; i++) prod *= (1.f - t[i]);
    }
    segprod[seg][b] = prod;
    __syncthreads();

    float cp = 1.f;
    for (int s = 0; s < seg; s++) cp *= segprod[s][b];

    float run = 0.f;
    for (int i0 = 0; i0 < SL; i0 += 8) {
        float t[8];
#pragma unroll
        for (int i = 0; i < 8; i++) t[i] = g_p[(s0 + i0 + i) * B + b];
#pragma unroll
        for (int i = 0; i < 8; i++) {
            const int s = s0 + i0 + i;
            const float al = t[i] * cp;
            cp *= (1.f - t[i]);
            alpha[s * B + b] = al;
            if (s < S - 1) run += al;
        }
    }
    segsum[seg][b] = run;
    __syncthreads();

    if (tid < 32) {
        float tot = 0.f;
#pragma unroll
        for (int s = 0; s < 32; s++) tot += segsum[s][tid];
        tot = fminf(fmaxf(tot, 0.f), 1.f);
        alpha[(S - 1) * B + tid] = 1.f - tot;
    }
}

// ---------------- Kernel 4: context partials (fp16 enc) ----------------
__global__ void k_ctx(const float* __restrict__ alpha) {
    const int sc = blockIdx.x;
    const int b = blockIdx.y;
    const int tid = threadIdx.x;           // 128 threads, 8 elems each
    const int s0 = sc * (S / SCH);
    float acc[8];
#pragma unroll
    for (int k = 0; k < 8; k++) acc[k] = 0.f;
#pragma unroll 4
    for (int s = s0; s < s0 + S / SCH; s++) {
        const float al = __ldg(&alpha[s * B + b]);
        const uint4 u = *(const uint4*)&g_encH[(size_t)(s * B + b) * E + tid * 8];
        const __half2* hp = (const __half2*)&u;
#pragma unroll
        for (int k = 0; k < 4; k++) {
            const float2 f = __half22float2(hp[k]);
            acc[2 * k + 0] = fmaf(al, f.x, acc[2 * k + 0]);
            acc[2 * k + 1] = fmaf(al, f.y, acc[2 * k + 1]);
        }
    }
    float* dst = g_ctx + ((size_t)(sc * B + b)) * E + tid * 8;
    *(float4*)dst       = make_float4(acc[0], acc[1], acc[2], acc[3]);
    *(float4*)(dst + 4) = make_float4(acc[4], acc[5], acc[6], acc[7]);
}

// ---------------- Kernel 5: reduce context partials ----------------
__global__ void k_ctxred(float* __restrict__ out) {
    const int i = blockIdx.x * 256 + threadIdx.x;
    if (i >= B * E) return;
    float s = 0.f;
#pragma unroll
    for (int c = 0; c < SCH; c++) s += g_ctx[(size_t)c * B * E + i];
    out[i] = s;
}

// ---------------------------------------------------------------------------
extern "C" void kernel_launch(void* const* d_in, const int* in_sizes, int n_in,
                              void* d_out, int out_size) {
    const float* dec   = (const float*)d_in[0];
    const float* enc   = (const float*)d_in[1];
    const float* noise = (const float*)d_in[2];
    const float* Wdec  = (const float*)d_in[3];
    const float* Wenc  = (const float*)d_in[4];
    const float* bias  = (const float*)d_in[5];
    const float* v     = (const float*)d_in[6];

    float* out       = (float*)d_out;             // [B*E] weighted_context
    float* alpha_out = out + B * E;               // [S*B] alpha

    cudaFuncSetAttribute(k_energy, cudaFuncAttributeMaxDynamicSharedMemorySize,
                         SMEM_BYTES);

    k_prep_enc<<<(int)(((size_t)R * E) / 2048), 256>>>(enc);
    k_prep_wt<<<dim3(A / 32, E / 32), dim3(32, 8)>>>(Wenc);
    k_decproj1<<<dim3(B, 8), 256>>>(dec, Wdec);
    k_decproj2<<<(B * A) / 256, 256>>>(bias);

    k_energy<<<R / BM, 256, SMEM_BYTES>>>(v, noise);

    k_scan<<<1, 1024>>>(alpha_out);

    dim3 gc(SCH, B);
    k_ctx<<<gc, 128>>>(alpha_out);

    k_ctxred<<<(B * E) / 256, 256>>>(out);
}

// round 10
// speedup vs baseline: 4.8459x; 1.0285x over previous
#include <cuda_runtime.h>
#include <cuda_fp16.h>
#include <cstdint>
#include <math.h>

static constexpr int S = 2048;
static constexpr int B = 32;
static constexpr int E = 1024;
static constexpr int A = 1024;
static constexpr int D = 1024;
static constexpr int R = S * B;

static constexpr int BM = 256, BN = 128;
static constexpr int BKC = 64;              // k per chunk
static constexpr int CHUNKS = E / BKC;      // 16
static constexpr int NPASS = A / BN;        // 8
static constexpr int GTOT = NPASS * CHUNKS; // 128 global chunks
static constexpr int SCH = 16;

// smem: 3 stages x (32KB A + 16KB B) + reduction
static constexpr int STAGE_A = 32768;
static constexpr int STAGE_B = 16384;
static constexpr int STAGE   = STAGE_A + STAGE_B;      // 49152
static constexpr int SM_RED  = 3 * STAGE;              // 147456
static constexpr int SMEM_BYTES = SM_RED + 256 * 2 * 4; // 149504

__device__ float g_z0[B * A];
__device__ float g_zpart[8][B * A];
__device__ float g_p[R];
__device__ float g_ctx[SCH * B * E];
__device__ __align__(16) __half g_encH[(size_t)R * E];    // 128 MB scratch
__device__ __align__(16) __half g_WencTH[(size_t)A * E];  // [a][e] fp16

__device__ __forceinline__ uint32_t smem_u32(const void* p) {
    uint32_t a;
    asm("{ .reg .u64 t; cvta.to.shared.u64 t, %1; cvt.u32.u64 %0, t; }"
        : "=r"(a) : "l"(p));
    return a;
}

#define CP16(dst, src) \
    asm volatile("cp.async.cg.shared.global [%0], [%1], 16;" \
                 :: "r"(dst), "l"(src))
#define CP_COMMIT() asm volatile("cp.async.commit_group;" ::: "memory")
#define CP_WAIT1()  asm volatile("cp.async.wait_group 1;" ::: "memory")

#define LDMX4(r0, r1, r2, r3, addr) \
    asm volatile("ldmatrix.sync.aligned.m8n8.x4.shared.b16 {%0,%1,%2,%3}, [%4];" \
                 : "=r"(r0), "=r"(r1), "=r"(r2), "=r"(r3) : "r"(addr))

__device__ __forceinline__ float fast_tanh(float x) {
    float e, r;
    asm("ex2.approx.f32 %0, %1;" : "=f"(e) : "f"(x * 2.885390082f));
    asm("rcp.approx.f32 %0, %1;" : "=f"(r) : "f"(e + 1.f));
    return fmaf(-2.f, r, 1.f);
}

// ---------------- Kernel 0a: enc -> fp16 ----------------
__global__ void k_prep_enc(const float* __restrict__ enc) {
    const size_t i = ((size_t)blockIdx.x * 256 + threadIdx.x) * 8;
    const float4 f0 = *(const float4*)(enc + i);
    const float4 f1 = *(const float4*)(enc + i + 4);
    __half2 h[4];
    h[0] = __floats2half2_rn(f0.x, f0.y);
    h[1] = __floats2half2_rn(f0.z, f0.w);
    h[2] = __floats2half2_rn(f1.x, f1.y);
    h[3] = __floats2half2_rn(f1.z, f1.w);
    *(uint4*)&g_encH[i] = *(uint4*)h;
}

// ---------------- Kernel 0b: WencTH[a][e] = (half)Wenc[e][a] ----------------
__global__ void k_prep_wt(const float* __restrict__ Wenc) {
    __shared__ float t[32][33];
    const int bx = blockIdx.x * 32;   // a
    const int by = blockIdx.y * 32;   // e
    const int x = threadIdx.x, y = threadIdx.y;
#pragma unroll
    for (int i = 0; i < 32; i += 8)
        t[y + i][x] = Wenc[(size_t)(by + y + i) * A + bx + x];
    __syncthreads();
#pragma unroll
    for (int i = 0; i < 32; i += 8)
        g_WencTH[(size_t)(bx + y + i) * E + by + x] = __float2half_rn(t[x][y + i]);
}

// ---------------- Kernel 1a: z0 partials (K-split x8) ----------------
__global__ void k_decproj1(const float* __restrict__ dec,
                           const float* __restrict__ Wdec) {
    __shared__ float sd[128];
    const int b = blockIdx.x, ks = blockIdx.y;
    const int tid = threadIdx.x;
    if (tid < 128) sd[tid] = dec[b * D + ks * 128 + tid];
    __syncthreads();
    float a0 = 0.f, a1 = 0.f, a2 = 0.f, a3 = 0.f;
#pragma unroll 4
    for (int e = 0; e < 128; e++) {
        const float dv = sd[e];
        const float* w = Wdec + (size_t)(ks * 128 + e) * A + tid;
        a0 += dv * w[0];   a1 += dv * w[256];
        a2 += dv * w[512]; a3 += dv * w[768];
    }
    float* zp = g_zpart[ks] + b * A + tid;
    zp[0] = a0; zp[256] = a1; zp[512] = a2; zp[768] = a3;
}

// ---------------- Kernel 1b: z0 = sum partials + bias ----------------
__global__ void k_decproj2(const float* __restrict__ bias) {
    const int i = blockIdx.x * 256 + threadIdx.x;
    float s = bias[i & (A - 1)];
#pragma unroll
    for (int ks = 0; ks < 8; ks++) s += g_zpart[ks][i];
    g_z0[i] = s;
}

// ---------------- k_energy loader ----------------
__device__ __forceinline__ void issue_stage(int g, int r0, int lm, int cb,
                                            uint32_t sb) {
    const int np = g >> 4, ch = g & 15;
    const int stg = (g % 3) * STAGE;
    // A: 256 rows, this thread does rows lm and lm+128
#pragma unroll
    for (int h = 0; h < 2; h++) {
        const int row = lm + h * 128;
        const __half* srcA = g_encH + (size_t)(r0 + row) * E + ch * BKC + cb * 8;
        const uint32_t dA = sb + stg + row * 128;
        const int r7 = row & 7;
#pragma unroll
        for (int j = 0; j < 4; j++)
            CP16(dA + (((cb + j) ^ r7) * 16), srcA + j * 8);
    }
    // B: 128 rows
    {
        const __half* srcB = g_WencTH + (size_t)(np * BN + lm) * E + ch * BKC + cb * 8;
        const uint32_t dB = sb + stg + STAGE_A + lm * 128;
        const int r7 = lm & 7;
#pragma unroll
        for (int j = 0; j < 4; j++)
            CP16(dB + (((cb + j) ^ r7) * 16), srcB + j * 8);
    }
}

// ---------------- Kernel 2: fp16 mma energy -> p ----------------
__global__ __launch_bounds__(256)
void k_energy(const float* __restrict__ v, const float* __restrict__ noise) {
    extern __shared__ __align__(1024) char smem[];
    const uint32_t sb = smem_u32(smem);
    float* sred = (float*)(smem + SM_RED);

    const int tid = threadIdx.x;
    const int lane = tid & 31, w = tid >> 5;
    const int wm = w >> 1, wn = w & 1;        // 4 x 2 warp grid, tile 64x64
    const int qr = lane >> 2, qc = lane & 3;
    const int r0 = blockIdx.x * BM;

    // ldmatrix lane geometry
    const int t8 = lane >> 3, rr = lane & 7;
    const int ctA = t8 >> 1;
    const int ctB = t8 & 1;
    int mrowA[4], nrowB[4];
#pragma unroll
    for (int mt = 0; mt < 4; mt++) mrowA[mt] = wm * 64 + mt * 16 + (t8 & 1) * 8 + rr;
#pragma unroll
    for (int np = 0; np < 4; np++) nrowB[np] = wn * 64 + np * 16 + (t8 >> 1) * 8 + rr;

    // cp.async loader geometry
    const int lm = tid >> 1;
    const int cb = (tid & 1) * 4;

    float ereg[8];
#pragma unroll
    for (int q = 0; q < 8; q++) ereg[q] = 0.f;
    float c[4][8][4];
#pragma unroll
    for (int mt = 0; mt < 4; mt++)
#pragma unroll
        for (int nt = 0; nt < 8; nt++)
#pragma unroll
            for (int q = 0; q < 4; q++) c[mt][nt][q] = 0.f;

    issue_stage(0, r0, lm, cb, sb); CP_COMMIT();
    issue_stage(1, r0, lm, cb, sb); CP_COMMIT();

#pragma unroll 1
    for (int g = 0; g < GTOT; g++) {
        CP_WAIT1();
        __syncthreads();

        const uint32_t aB = sb + (g % 3) * STAGE;
        const uint32_t bB = aB + STAGE_A;
#pragma unroll
        for (int ks = 0; ks < 4; ks++) {
            uint32_t af[4][4], bf[8][2];
#pragma unroll
            for (int mt = 0; mt < 4; mt++) {
                const int cc = ks * 2 + ctA;
                const uint32_t addr =
                    aB + mrowA[mt] * 128 + ((cc ^ (mrowA[mt] & 7)) * 16);
                LDMX4(af[mt][0], af[mt][1], af[mt][2], af[mt][3], addr);
            }
#pragma unroll
            for (int ntp = 0; ntp < 4; ntp++) {
                const int cc = ks * 2 + ctB;
                const uint32_t addr =
                    bB + nrowB[ntp] * 128 + ((cc ^ (nrowB[ntp] & 7)) * 16);
                LDMX4(bf[2 * ntp][0], bf[2 * ntp][1],
                      bf[2 * ntp + 1][0], bf[2 * ntp + 1][1], addr);
            }
#pragma unroll
            for (int mt = 0; mt < 4; mt++)
#pragma unroll
                for (int nt = 0; nt < 8; nt++) {
                    asm volatile(
                        "mma.sync.aligned.m16n8k16.row.col.f32.f16.f16.f32 "
                        "{%0,%1,%2,%3}, {%4,%5,%6,%7}, {%8,%9}, {%0,%1,%2,%3};"
                        : "+f"(c[mt][nt][0]), "+f"(c[mt][nt][1]),
                          "+f"(c[mt][nt][2]), "+f"(c[mt][nt][3])
                        : "r"(af[mt][0]), "r"(af[mt][1]),
                          "r"(af[mt][2]), "r"(af[mt][3]),
                          "r"(bf[nt][0]), "r"(bf[nt][1]));
                }
        }

        if (g + 2 < GTOT) issue_stage(g + 2, r0, lm, cb, sb);
        CP_COMMIT();   // keep group counting uniform

        if ((g & 15) == 15) {
            // epilogue for pass np = g>>4: +z0, tanh, dot v (z0/v via L2)
            const int n0 = (g >> 4) * BN;
#pragma unroll
            for (int mt = 0; mt < 4; mt++)
#pragma unroll
                for (int half = 0; half < 2; half++) {
                    const int bz = (mt * 16 + half * 8 + qr) & 31;
                    const float* zr = g_z0 + bz * A + n0;
                    float acc = 0.f;
#pragma unroll
                    for (int nt = 0; nt < 8; nt++) {
                        const int lc = wn * 64 + nt * 8 + 2 * qc;
                        const float x0 = c[mt][nt][half * 2 + 0] + __ldg(zr + lc);
                        const float x1 = c[mt][nt][half * 2 + 1] + __ldg(zr + lc + 1);
                        acc = fmaf(__ldg(&v[n0 + lc]),     fast_tanh(x0), acc);
                        acc = fmaf(__ldg(&v[n0 + lc + 1]), fast_tanh(x1), acc);
                    }
                    ereg[mt * 2 + half] += acc;
#pragma unroll
                    for (int nt = 0; nt < 8; nt++) {
                        c[mt][nt][half * 2 + 0] = 0.f;
                        c[mt][nt][half * 2 + 1] = 0.f;
                    }
                }
        }
    }

    // quad reduce across qc
#pragma unroll
    for (int q = 0; q < 8; q++) {
        ereg[q] += __shfl_xor_sync(0xFFFFFFFFu, ereg[q], 1);
        ereg[q] += __shfl_xor_sync(0xFFFFFFFFu, ereg[q], 2);
    }
    __syncthreads();
    if (qc == 0) {
#pragma unroll
        for (int mt = 0; mt < 4; mt++)
#pragma unroll
            for (int half = 0; half < 2; half++) {
                const int row = wm * 64 + mt * 16 + half * 8 + qr;
                sred[row * 2 + wn] = ereg[mt * 2 + half];
            }
    }
    __syncthreads();
    {
        const float e = sred[tid * 2] + sred[tid * 2 + 1];
        const float x = e + noise[r0 + tid];
        g_p[r0 + tid] = 1.f / (1.f + expf(-x));
    }
}

// ---------------- Kernel 3: parallel monotonic scan ----------------
__global__ void k_scan(float* __restrict__ alpha) {
    __shared__ float segprod[32][33];
    __shared__ float segsum[32][33];
    const int tid = threadIdx.x;
    const int b = tid & 31, seg = tid >> 5;
    const int SL = S / 32;
    const int s0 = seg * SL;

    float prod = 1.f;
    for (int i0 = 0; i0 < SL; i0 += 8) {
        float t[8];
#pragma unroll
        for (int i = 0; i < 8; i++) t[i] = g_p[(s0 + i0 + i) * B + b];
#pragma unroll
        for (int i = 0; i < 8; i++) prod *= (1.f - t[i]);
    }
    segprod[seg][b] = prod;
    __syncthreads();

    float cp = 1.f;
    for (int s = 0; s < seg; s++) cp *= segprod[s][b];

    float run = 0.f;
    for (int i0 = 0; i0 < SL; i0 += 8) {
        float t[8];
#pragma unroll
        for (int i = 0; i < 8; i++) t[i] = g_p[(s0 + i0 + i) * B + b];
#pragma unroll
        for (int i = 0; i < 8; i++) {
            const int s = s0 + i0 + i;
            const float al = t[i] * cp;
            cp *= (1.f - t[i]);
            alpha[s * B + b] = al;
            if (s < S - 1) run += al;
        }
    }
    segsum[seg][b] = run;
    __syncthreads();

    if (tid < 32) {
        float tot = 0.f;
#pragma unroll
        for (int s = 0; s < 32; s++) tot += segsum[s][tid];
        tot = fminf(fmaxf(tot, 0.f), 1.f);
        alpha[(S - 1) * B + tid] = 1.f - tot;
    }
}

// ---------------- Kernel 4: context partials (fp16 enc) ----------------
__global__ void k_ctx(const float* __restrict__ alpha) {
    const int sc = blockIdx.x;
    const int b = blockIdx.y;
    const int tid = threadIdx.x;           // 128 threads, 8 elems each
    const int s0 = sc * (S / SCH);
    float acc[8];
#pragma unroll
    for (int k = 0; k < 8; k++) acc[k] = 0.f;
#pragma unroll 4
    for (int s = s0; s < s0 + S / SCH; s++) {
        const float al = __ldg(&alpha[s * B + b]);
        const uint4 u = *(const uint4*)&g_encH[(size_t)(s * B + b) * E + tid * 8];
        const __half2* hp = (const __half2*)&u;
#pragma unroll
        for (int k = 0; k < 4; k++) {
            const float2 f = __half22float2(hp[k]);
            acc[2 * k + 0] = fmaf(al, f.x, acc[2 * k + 0]);
            acc[2 * k + 1] = fmaf(al, f.y, acc[2 * k + 1]);
        }
    }
    float* dst = g_ctx + ((size_t)(sc * B + b)) * E + tid * 8;
    *(float4*)dst       = make_float4(acc[0], acc[1], acc[2], acc[3]);
    *(float4*)(dst + 4) = make_float4(acc[4], acc[5], acc[6], acc[7]);
}

// ---------------- Kernel 5: reduce context partials ----------------
__global__ void k_ctxred(float* __restrict__ out) {
    const int i = blockIdx.x * 256 + threadIdx.x;
    if (i >= B * E) return;
    float s = 0.f;
#pragma unroll
    for (int c = 0; c < SCH; c++) s += g_ctx[(size_t)c * B * E + i];
    out[i] = s;
}

// ---------------------------------------------------------------------------
extern "C" void kernel_launch(void* const* d_in, const int* in_sizes, int n_in,
                              void* d_out, int out_size) {
    const float* dec   = (const float*)d_in[0];
    const float* enc   = (const float*)d_in[1];
    const float* noise = (const float*)d_in[2];
    const float* Wdec  = (const float*)d_in[3];
    const float* Wenc  = (const float*)d_in[4];
    const float* bias  = (const float*)d_in[5];
    const float* v     = (const float*)d_in[6];

    float* out       = (float*)d_out;             // [B*E] weighted_context
    float* alpha_out = out + B * E;               // [S*B] alpha

    cudaFuncSetAttribute(k_energy, cudaFuncAttributeMaxDynamicSharedMemorySize,
                         SMEM_BYTES);

    k_prep_enc<<<(int)(((size_t)R * E) / 2048), 256>>>(enc);
    k_prep_wt<<<dim3(A / 32, E / 32), dim3(32, 8)>>>(Wenc);
    k_decproj1<<<dim3(B, 8), 256>>>(dec, Wdec);
    k_decproj2<<<(B * A) / 256, 256>>>(bias);

    k_energy<<<R / BM, 256, SMEM_BYTES>>>(v, noise);

    k_scan<<<1, 1024>>>(alpha_out);

    dim3 gc(SCH, B);
    k_ctx<<<gc, 128>>>(alpha_out);

    k_ctxred<<<(B * E) / 256, 256>>>(out);
}

// round 11
// speedup vs baseline: 5.3759x; 1.1094x over previous
#include <cuda_runtime.h>
#include <cuda_fp16.h>
#include <cstdint>
#include <math.h>

static constexpr int S = 2048;
static constexpr int B = 32;
static constexpr int E = 1024;
static constexpr int A = 1024;
static constexpr int D = 1024;
static constexpr int R = S * B;

static constexpr int BM = 256, BN = 128;
static constexpr int BKC = 64;              // k per chunk
static constexpr int CHUNKS = E / BKC;      // 16
static constexpr int NPASS = A / BN;        // 8
static constexpr int GTOT = NPASS * CHUNKS; // 128 global chunks
static constexpr int SCH = 16;
static constexpr int NTHR = 512;

// smem: 3 stages x (32KB A + 16KB B) + reduction
static constexpr int STAGE_A = 32768;
static constexpr int STAGE_B = 16384;
static constexpr int STAGE   = STAGE_A + STAGE_B;        // 49152
static constexpr int SM_RED  = 3 * STAGE;                // 147456
static constexpr int SMEM_BYTES = SM_RED + 256 * 4 * 4;  // 151552

__device__ float g_z0[B * A];
__device__ float g_zpart[8][B * A];
__device__ float g_p[R];
__device__ float g_ctx[SCH * B * E];
__device__ __align__(16) __half g_encH[(size_t)R * E];    // 128 MB scratch
__device__ __align__(16) __half g_WencTH[(size_t)A * E];  // [a][e] fp16

__device__ __forceinline__ uint32_t smem_u32(const void* p) {
    uint32_t a;
    asm("{ .reg .u64 t; cvta.to.shared.u64 t, %1; cvt.u32.u64 %0, t; }"
        : "=r"(a) : "l"(p));
    return a;
}

#define CP16(dst, src) \
    asm volatile("cp.async.cg.shared.global [%0], [%1], 16;" \
                 :: "r"(dst), "l"(src))
#define CP_COMMIT() asm volatile("cp.async.commit_group;" ::: "memory")
#define CP_WAIT1()  asm volatile("cp.async.wait_group 1;" ::: "memory")

#define LDMX4(r0, r1, r2, r3, addr) \
    asm volatile("ldmatrix.sync.aligned.m8n8.x4.shared.b16 {%0,%1,%2,%3}, [%4];" \
                 : "=r"(r0), "=r"(r1), "=r"(r2), "=r"(r3) : "r"(addr))

__device__ __forceinline__ float fast_tanh(float x) {
    float e, r;
    asm("ex2.approx.f32 %0, %1;" : "=f"(e) : "f"(x * 2.885390082f));
    asm("rcp.approx.f32 %0, %1;" : "=f"(r) : "f"(e + 1.f));
    return fmaf(-2.f, r, 1.f);
}

// ---------------- Kernel 0a: enc -> fp16 ----------------
__global__ void k_prep_enc(const float* __restrict__ enc) {
    const size_t i = ((size_t)blockIdx.x * 256 + threadIdx.x) * 8;
    const float4 f0 = *(const float4*)(enc + i);
    const float4 f1 = *(const float4*)(enc + i + 4);
    __half2 h[4];
    h[0] = __floats2half2_rn(f0.x, f0.y);
    h[1] = __floats2half2_rn(f0.z, f0.w);
    h[2] = __floats2half2_rn(f1.x, f1.y);
    h[3] = __floats2half2_rn(f1.z, f1.w);
    *(uint4*)&g_encH[i] = *(uint4*)h;
}

// ---------------- Kernel 0b: WencTH[a][e] = (half)Wenc[e][a] ----------------
__global__ void k_prep_wt(const float* __restrict__ Wenc) {
    __shared__ float t[32][33];
    const int bx = blockIdx.x * 32;   // a
    const int by = blockIdx.y * 32;   // e
    const int x = threadIdx.x, y = threadIdx.y;
#pragma unroll
    for (int i = 0; i < 32; i += 8)
        t[y + i][x] = Wenc[(size_t)(by + y + i) * A + bx + x];
    __syncthreads();
#pragma unroll
    for (int i = 0; i < 32; i += 8)
        g_WencTH[(size_t)(bx + y + i) * E + by + x] = __float2half_rn(t[x][y + i]);
}

// ---------------- Kernel 1a: z0 partials (K-split x8) ----------------
__global__ void k_decproj1(const float* __restrict__ dec,
                           const float* __restrict__ Wdec) {
    __shared__ float sd[128];
    const int b = blockIdx.x, ks = blockIdx.y;
    const int tid = threadIdx.x;
    if (tid < 128) sd[tid] = dec[b * D + ks * 128 + tid];
    __syncthreads();
    float a0 = 0.f, a1 = 0.f, a2 = 0.f, a3 = 0.f;
#pragma unroll 4
    for (int e = 0; e < 128; e++) {
        const float dv = sd[e];
        const float* w = Wdec + (size_t)(ks * 128 + e) * A + tid;
        a0 += dv * w[0];   a1 += dv * w[256];
        a2 += dv * w[512]; a3 += dv * w[768];
    }
    float* zp = g_zpart[ks] + b * A + tid;
    zp[0] = a0; zp[256] = a1; zp[512] = a2; zp[768] = a3;
}

// ---------------- Kernel 1b: z0 = sum partials + bias ----------------
__global__ void k_decproj2(const float* __restrict__ bias) {
    const int i = blockIdx.x * 256 + threadIdx.x;
    float s = bias[i & (A - 1)];
#pragma unroll
    for (int ks = 0; ks < 8; ks++) s += g_zpart[ks][i];
    g_z0[i] = s;
}

// ---------------- k_energy loader (512 threads) ----------------
__device__ __forceinline__ void issue_stage(int g, int r0, int tid,
                                            uint32_t sb) {
    const int np = g >> 4, ch = g & 15;
    const int stg = (g % 3) * STAGE;
    // A: 256 rows x 128B, 4 x 16B per thread
    {
        const int row = tid >> 1, cb = (tid & 1) * 4;
        const __half* srcA = g_encH + (size_t)(r0 + row) * E + ch * BKC + cb * 8;
        const uint32_t dA = sb + stg + row * 128;
        const int r7 = row & 7;
#pragma unroll
        for (int j = 0; j < 4; j++)
            CP16(dA + (((cb + j) ^ r7) * 16), srcA + j * 8);
    }
    // B: 128 rows x 128B, 2 x 16B per thread
    {
        const int row = tid >> 2, cb = (tid & 3) * 2;
        const __half* srcB = g_WencTH + (size_t)(np * BN + row) * E + ch * BKC + cb * 8;
        const uint32_t dB = sb + stg + STAGE_A + row * 128;
        const int r7 = row & 7;
#pragma unroll
        for (int j = 0; j < 2; j++)
            CP16(dB + (((cb + j) ^ r7) * 16), srcB + j * 8);
    }
}

// ---------------- Kernel 2: fp16 mma energy -> p ----------------
__global__ __launch_bounds__(NTHR)
void k_energy(const float* __restrict__ v, const float* __restrict__ noise) {
    extern __shared__ __align__(1024) char smem[];
    const uint32_t sb = smem_u32(smem);
    float* sred = (float*)(smem + SM_RED);

    const int tid = threadIdx.x;
    const int lane = tid & 31, w = tid >> 5;
    const int wm = w >> 2, wn = w & 3;        // 4 x 4 warp grid, tile 64x32
    const int qr = lane >> 2, qc = lane & 3;
    const int r0 = blockIdx.x * BM;

    // ldmatrix lane geometry (identical formulas to validated rounds 7-9)
    const int t8 = lane >> 3, rr = lane & 7;
    const int ctA = t8 >> 1;
    const int ctB = t8 & 1;
    int mrowA[4], nrowB[2];
#pragma unroll
    for (int mt = 0; mt < 4; mt++) mrowA[mt] = wm * 64 + mt * 16 + (t8 & 1) * 8 + rr;
#pragma unroll
    for (int np = 0; np < 2; np++) nrowB[np] = wn * 32 + np * 16 + (t8 >> 1) * 8 + rr;

    float ereg[8];
#pragma unroll
    for (int q = 0; q < 8; q++) ereg[q] = 0.f;
    float c[4][4][4];
#pragma unroll
    for (int mt = 0; mt < 4; mt++)
#pragma unroll
        for (int nt = 0; nt < 4; nt++)
#pragma unroll
            for (int q = 0; q < 4; q++) c[mt][nt][q] = 0.f;

    issue_stage(0, r0, tid, sb); CP_COMMIT();
    issue_stage(1, r0, tid, sb); CP_COMMIT();

#pragma unroll 1
    for (int g = 0; g < GTOT; g++) {
        CP_WAIT1();
        __syncthreads();

        const uint32_t aB = sb + (g % 3) * STAGE;
        const uint32_t bB = aB + STAGE_A;
#pragma unroll
        for (int ks = 0; ks < 4; ks++) {
            uint32_t af[4][4], bf[4][2];
#pragma unroll
            for (int mt = 0; mt < 4; mt++) {
                const int cc = ks * 2 + ctA;
                const uint32_t addr =
                    aB + mrowA[mt] * 128 + ((cc ^ (mrowA[mt] & 7)) * 16);
                LDMX4(af[mt][0], af[mt][1], af[mt][2], af[mt][3], addr);
            }
#pragma unroll
            for (int ntp = 0; ntp < 2; ntp++) {
                const int cc = ks * 2 + ctB;
                const uint32_t addr =
                    bB + nrowB[ntp] * 128 + ((cc ^ (nrowB[ntp] & 7)) * 16);
                LDMX4(bf[2 * ntp][0], bf[2 * ntp][1],
                      bf[2 * ntp + 1][0], bf[2 * ntp + 1][1], addr);
            }
#pragma unroll
            for (int mt = 0; mt < 4; mt++)
#pragma unroll
                for (int nt = 0; nt < 4; nt++) {
                    asm volatile(
                        "mma.sync.aligned.m16n8k16.row.col.f32.f16.f16.f32 "
                        "{%0,%1,%2,%3}, {%4,%5,%6,%7}, {%8,%9}, {%0,%1,%2,%3};"
                        : "+f"(c[mt][nt][0]), "+f"(c[mt][nt][1]),
                          "+f"(c[mt][nt][2]), "+f"(c[mt][nt][3])
                        : "r"(af[mt][0]), "r"(af[mt][1]),
                          "r"(af[mt][2]), "r"(af[mt][3]),
                          "r"(bf[nt][0]), "r"(bf[nt][1]));
                }
        }

        if (g + 2 < GTOT) issue_stage(g + 2, r0, tid, sb);
        CP_COMMIT();   // keep group counting uniform

        if ((g & 15) == 15) {
            // epilogue for pass np = g>>4: +z0, tanh, dot v (z0/v via L1/L2)
            const int n0 = (g >> 4) * BN;
#pragma unroll
            for (int mt = 0; mt < 4; mt++)
#pragma unroll
                for (int half = 0; half < 2; half++) {
                    const int bz = (mt * 16 + half * 8 + qr) & 31;
                    const float* zr = g_z0 + bz * A + n0;
                    float acc = 0.f;
#pragma unroll
                    for (int nt = 0; nt < 4; nt++) {
                        const int lc = wn * 32 + nt * 8 + 2 * qc;
                        const float x0 = c[mt][nt][half * 2 + 0] + __ldg(zr + lc);
                        const float x1 = c[mt][nt][half * 2 + 1] + __ldg(zr + lc + 1);
                        acc = fmaf(__ldg(&v[n0 + lc]),     fast_tanh(x0), acc);
                        acc = fmaf(__ldg(&v[n0 + lc + 1]), fast_tanh(x1), acc);
                    }
                    ereg[mt * 2 + half] += acc;
#pragma unroll
                    for (int nt = 0; nt < 4; nt++) {
                        c[mt][nt][half * 2 + 0] = 0.f;
                        c[mt][nt][half * 2 + 1] = 0.f;
                    }
                }
        }
    }

    // quad reduce across qc (lanes sharing a row differ in qc only)
#pragma unroll
    for (int q = 0; q < 8; q++) {
        ereg[q] += __shfl_xor_sync(0xFFFFFFFFu, ereg[q], 1);
        ereg[q] += __shfl_xor_sync(0xFFFFFFFFu, ereg[q], 2);
    }
    __syncthreads();
    if (qc == 0) {
#pragma unroll
        for (int mt = 0; mt < 4; mt++)
#pragma unroll
            for (int half = 0; half < 2; half++) {
                const int row = wm * 64 + mt * 16 + half * 8 + qr;
                sred[row * 4 + wn] = ereg[mt * 2 + half];
            }
    }
    __syncthreads();
    if (tid < BM) {
        const float e = sred[tid * 4] + sred[tid * 4 + 1] +
                        sred[tid * 4 + 2] + sred[tid * 4 + 3];
        const float x = e + noise[r0 + tid];
        g_p[r0 + tid] = 1.f / (1.f + expf(-x));
    }
}

// ---------------- Kernel 3: parallel monotonic scan ----------------
__global__ void k_scan(float* __restrict__ alpha) {
    __shared__ float segprod[32][33];
    __shared__ float segsum[32][33];
    const int tid = threadIdx.x;
    const int b = tid & 31, seg = tid >> 5;
    const int SL = S / 32;
    const int s0 = seg * SL;

    float prod = 1.f;
    for (int i0 = 0; i0 < SL; i0 += 8) {
        float t[8];
#pragma unroll
        for (int i = 0; i < 8; i++) t[i] = g_p[(s0 + i0 + i) * B + b];
#pragma unroll
        for (int i = 0; i < 8; i++) prod *= (1.f - t[i]);
    }
    segprod[seg][b] = prod;
    __syncthreads();

    float cp = 1.f;
    for (int s = 0; s < seg; s++) cp *= segprod[s][b];

    float run = 0.f;
    for (int i0 = 0; i0 < SL; i0 += 8) {
        float t[8];
#pragma unroll
        for (int i = 0; i < 8; i++) t[i] = g_p[(s0 + i0 + i) * B + b];
#pragma unroll
        for (int i = 0; i < 8; i++) {
            const int s = s0 + i0 + i;
            const float al = t[i] * cp;
            cp *= (1.f - t[i]);
            alpha[s * B + b] = al;
            if (s < S - 1) run += al;
        }
    }
    segsum[seg][b] = run;
    __syncthreads();

    if (tid < 32) {
        float tot = 0.f;
#pragma unroll
        for (int s = 0; s < 32; s++) tot += segsum[s][tid];
        tot = fminf(fmaxf(tot, 0.f), 1.f);
        alpha[(S - 1) * B + tid] = 1.f - tot;
    }
}

// ---------------- Kernel 4: context partials (fp16 enc) ----------------
__global__ void k_ctx(const float* __restrict__ alpha) {
    const int sc = blockIdx.x;
    const int b = blockIdx.y;
    const int tid = threadIdx.x;           // 128 threads, 8 elems each
    const int s0 = sc * (S / SCH);
    float acc[8];
#pragma unroll
    for (int k = 0; k < 8; k++) acc[k] = 0.f;
#pragma unroll 4
    for (int s = s0; s < s0 + S / SCH; s++) {
        const float al = __ldg(&alpha[s * B + b]);
        const uint4 u = *(const uint4*)&g_encH[(size_t)(s * B + b) * E + tid * 8];
        const __half2* hp = (const __half2*)&u;
#pragma unroll
        for (int k = 0; k < 4; k++) {
            const float2 f = __half22float2(hp[k]);
            acc[2 * k + 0] = fmaf(al, f.x, acc[2 * k + 0]);
            acc[2 * k + 1] = fmaf(al, f.y, acc[2 * k + 1]);
        }
    }
    float* dst = g_ctx + ((size_t)(sc * B + b)) * E + tid * 8;
    *(float4*)dst       = make_float4(acc[0], acc[1], acc[2], acc[3]);
    *(float4*)(dst + 4) = make_float4(acc[4], acc[5], acc[6], acc[7]);
}

// ---------------- Kernel 5: reduce context partials ----------------
__global__ void k_ctxred(float* __restrict__ out) {
    const int i = blockIdx.x * 256 + threadIdx.x;
    if (i >= B * E) return;
    float s = 0.f;
#pragma unroll
    for (int c = 0; c < SCH; c++) s += g_ctx[(size_t)c * B * E + i];
    out[i] = s;
}

// ---------------------------------------------------------------------------
extern "C" void kernel_launch(void* const* d_in, const int* in_sizes, int n_in,
                              void* d_out, int out_size) {
    const float* dec   = (const float*)d_in[0];
    const float* enc   = (const float*)d_in[1];
    const float* noise = (const float*)d_in[2];
    const float* Wdec  = (const float*)d_in[3];
    const float* Wenc  = (const float*)d_in[4];
    const float* bias  = (const float*)d_in[5];
    const float* v     = (const float*)d_in[6];

    float* out       = (float*)d_out;             // [B*E] weighted_context
    float* alpha_out = out + B * E;               // [S*B] alpha

    cudaFuncSetAttribute(k_energy, cudaFuncAttributeMaxDynamicSharedMemorySize,
                         SMEM_BYTES);

    k_prep_enc<<<(int)(((size_t)R * E) / 2048), 256>>>(enc);
    k_prep_wt<<<dim3(A / 32, E / 32), dim3(32, 8)>>>(Wenc);
    k_decproj1<<<dim3(B, 8), 256>>>(dec, Wdec);
    k_decproj2<<<(B * A) / 256, 256>>>(bias);

    k_energy<<<R / BM, NTHR, SMEM_BYTES>>>(v, noise);

    k_scan<<<1, 1024>>>(alpha_out);

    dim3 gc(SCH, B);
    k_ctx<<<gc, 128>>>(alpha_out);

    k_ctxred<<<(B * E) / 256, 256>>>(out);
}